// round 13
// baseline (speedup 1.0000x reference)
#include <cuda_runtime.h>
#include <cstdint>

#define BATCH 4
#define SEQ   4096
#define CDIM  256
#define DDIM  32
#define TQ    128
#define TK    64
#define NT_TILES (SEQ / TK)
#define LOG2E 1.4426950408889634f

// ---- scratch ----
__device__ float g_q[BATCH * SEQ * DDIM];
__device__ float g_kth[BATCH * NT_TILES * 1024];   // K-hi bf16x2 words, KT tile layout (interleaved)
__device__ float g_ktl[BATCH * NT_TILES * 1024];   // K-lo
__device__ float g_vt[BATCH * CDIM * SEQ];         // V^T channel-major, keys interleaved per 64-tile

// ---- helpers ----
__device__ __forceinline__ unsigned long long pack2(float lo, float hi) {
    unsigned long long r;
    asm("mov.b64 %0, {%1, %2};" : "=l"(r) : "f"(lo), "f"(hi));
    return r;
}
__device__ __forceinline__ void unpack2(unsigned long long v, float& lo, float& hi) {
    asm("mov.b64 {%0, %1}, %2;" : "=f"(lo), "=f"(hi) : "l"(v));
}
__device__ __forceinline__ unsigned long long ffma2(unsigned long long a, unsigned long long b,
                                                    unsigned long long c) {
    unsigned long long d;
    asm("fma.rn.f32x2 %0, %1, %2, %3;" : "=l"(d) : "l"(a), "l"(b), "l"(c));
    return d;
}
__device__ __forceinline__ uint32_t smem_u32(const void* p) {
    uint32_t a;
    asm("{ .reg .u64 t; cvta.to.shared.u64 t, %1; cvt.u32.u64 %0, t; }" : "=r"(a) : "l"(p));
    return a;
}
__device__ __forceinline__ void cp_async16(uint32_t dst, const void* src) {
    asm volatile("cp.async.cg.shared.global [%0], [%1], 16;" :: "r"(dst), "l"(src));
}
__device__ __forceinline__ float ex2(float x) {
    float r;
    asm("ex2.approx.f32 %0, %1;" : "=f"(r) : "f"(x));
    return r;
}
__device__ __forceinline__ uint32_t bfpack(float lo, float hi) {
    uint32_t r;
    asm("cvt.rn.bf16x2.f32 %0, %1, %2;" : "=r"(r) : "f"(hi), "f"(lo));
    return r;
}
__device__ __forceinline__ uint32_t bftruncpack(float x0, float x1) {
    return __byte_perm(__float_as_uint(x0), __float_as_uint(x1), 0x7632);
}
__device__ __forceinline__ float bftrunc_res(float x) {
    return x - __uint_as_float(__float_as_uint(x) & 0xFFFF0000u);
}
__device__ __forceinline__ void mma8(float d[4], uint32_t a0, uint32_t a1, uint32_t a2,
                                     uint32_t a3, uint32_t b0, uint32_t b1) {
    asm volatile(
        "mma.sync.aligned.m16n8k8.row.col.f32.tf32.tf32.f32 "
        "{%0,%1,%2,%3}, {%4,%5,%6,%7}, {%8,%9}, {%0,%1,%2,%3};"
        : "+f"(d[0]), "+f"(d[1]), "+f"(d[2]), "+f"(d[3])
        : "r"(a0), "r"(a1), "r"(a2), "r"(a3), "r"(b0), "r"(b1));
}
__device__ __forceinline__ void mma16(float d[4], uint32_t a0, uint32_t a1, uint32_t a2,
                                      uint32_t a3, uint32_t b0, uint32_t b1) {
    asm volatile(
        "mma.sync.aligned.m16n8k16.row.col.f32.bf16.bf16.f32 "
        "{%0,%1,%2,%3}, {%4,%5,%6,%7}, {%8,%9}, {%0,%1,%2,%3};"
        : "+f"(d[0]), "+f"(d[1]), "+f"(d[2]), "+f"(d[3])
        : "r"(a0), "r"(a1), "r"(a2), "r"(a3), "r"(b0), "r"(b1));
}

// k-interleave within 8-blocks: order 0,4,1,5,2,6,3,7 -> pairs (k,k+4) adjacent
__device__ __forceinline__ int intl16(int w) { return (w & 8) | ((w & 3) << 1) | ((w >> 2) & 1); }
__device__ __forceinline__ int intl8b(int k) { return (k & ~7) | ((k & 3) << 1) | ((k >> 2) & 1); }

// ---- flash smem byte offsets ----
#define OFF_QH16 0          /* 8 KB */
#define OFF_QL16 8192       /* 8 KB */
#define OFF_KTH  16384      /* 4 KB */
#define OFF_KTL  20480      /* 4 KB */
#define OFF_P    24576      /* 32 KB */
#define OFF_V    57344      /* 2 x 64 KB */
#define OFF_L    188416
#define OFF_LP   188928
#define FLASH_SMEM 190976

// interleaved word-index layouts (pair-adjacent, bank-verified)
__device__ __forceinline__ int pQ16i(int r, int w)   { return r * 16 + (intl16(w) ^ ((r & 2) * 4)); }
__device__ __forceinline__ int pK16i(int key, int w) { return key * 16 + (intl16(w) ^ ((key & 2) * 4)); }
__device__ __forceinline__ int pPi(int r, int c)     { return r * 64 + (intl8b(c) ^ ((r & 3) * 8)); }

// ============================================================================
// Flash attention: bf16 3-term QK, tf32 PV; all fragment pairs via LDS.64.
// 256 threads = 8 warps: mw = wid&1 (64 rows), nw = wid>>1 (16 keys / 64 PV cols)
// ============================================================================
__global__ __launch_bounds__(256, 1)
void flash_mma(const float* __restrict__ Qg,
               const float* __restrict__ KTHg, const float* __restrict__ KTLg,
               const float* __restrict__ VTg, const float* __restrict__ X,
               float* __restrict__ Out) {
    extern __shared__ char smem[];
    uint32_t* sQh = (uint32_t*)(smem + OFF_QH16);
    uint32_t* sQl = (uint32_t*)(smem + OFF_QL16);
    uint32_t* sKh = (uint32_t*)(smem + OFF_KTH);
    uint32_t* sKl = (uint32_t*)(smem + OFF_KTL);
    uint32_t* sPu = (uint32_t*)(smem + OFF_P);
    uint32_t* sVu = (uint32_t*)(smem + OFF_V);
    float*    sL  = (float*)(smem + OFF_L);
    float*    sLp = (float*)(smem + OFF_LP);
    const uint32_t sb = smem_u32(smem);

    const int tid  = threadIdx.x;
    const int lane = tid & 31;
    const int wid  = tid >> 5;
    const int mw   = wid & 1;
    const int nw   = wid >> 1;
    const int g    = lane >> 2;
    const int l4   = lane & 3;
    const int b    = blockIdx.y;
    const int q0   = blockIdx.x * TQ;

    const float* Qb = Qg + ((size_t)b * SEQ + q0) * DDIM;
    const char*  KThb = (const char*)(KTHg + (size_t)b * NT_TILES * 1024);
    const char*  KTlb = (const char*)(KTLg + (size_t)b * NT_TILES * 1024);
    const float* VTb = VTg + (size_t)b * CDIM * SEQ;

    // ---- prologue ----
    if (tid < 128) sL[tid] = 0.0f;
    // Q: scale by log2e, bf16 hi/lo split, interleaved word layout
#pragma unroll
    for (int i = 0; i < 4; i++) {
        int idx = tid + i * 256;
        int r = idx >> 3, d4 = idx & 7;
        float4 v = *(const float4*)(Qb + r * DDIM + d4 * 4);
        v.x *= LOG2E; v.y *= LOG2E; v.z *= LOG2E; v.w *= LOG2E;
        uint32_t hi0 = bftruncpack(v.x, v.y);
        uint32_t hi1 = bftruncpack(v.z, v.w);
        uint32_t lo0 = bfpack(bftrunc_res(v.x), bftrunc_res(v.y));
        uint32_t lo1 = bfpack(bftrunc_res(v.z), bftrunc_res(v.w));
        int wa = pQ16i(r, 2 * d4);
        int wb = pQ16i(r, 2 * d4 + 1);
        sQh[wa] = hi0; sQh[wb] = hi1;
        sQl[wa] = lo0; sQl[wb] = lo1;
    }
    // KT(0) (raw image) + V^T(0) via cp.async
    {
        uint32_t off = (uint32_t)tid * 16u;
        cp_async16(sb + OFF_KTH + off, KThb + off);
        cp_async16(sb + OFF_KTL + off, KTlb + off);
    }
#pragma unroll
    for (int i = 0; i < 16; i++) {
        int f = tid + i * 256;
        int j4 = f & 15, ch = f >> 4;
        uint32_t dst = sb + OFF_V + (uint32_t)(ch * 64 + ((j4 * 4) ^ ((ch & 3) * 8))) * 4u;
        cp_async16(dst, VTb + (size_t)ch * SEQ + j4 * 4);
    }
    asm volatile("cp.async.commit_group;" ::: "memory");
    asm volatile("cp.async.wait_group 0;" ::: "memory");
    __syncthreads();

    float oa[4][8][4];
#pragma unroll
    for (int mt = 0; mt < 4; mt++)
#pragma unroll
        for (int nt = 0; nt < 8; nt++)
#pragma unroll
            for (int c = 0; c < 4; c++) oa[mt][nt][c] = 0.0f;

#pragma unroll 1
    for (int t = 0; t < NT_TILES; t++) {
        const int buf = t & 1;
        const bool have_next = (t + 1 < NT_TILES);

        if (have_next) {
            uint32_t vb0 = sb + OFF_V + (uint32_t)(1 - buf) * 65536u;
            const float* Vs = VTb + (size_t)(t + 1) * 64;
#pragma unroll
            for (int i = 0; i < 16; i++) {
                int f = tid + i * 256;
                int j4 = f & 15, ch = f >> 4;
                uint32_t dst = vb0 + (uint32_t)(ch * 64 + ((j4 * 4) ^ ((ch & 3) * 8))) * 4u;
                cp_async16(dst, Vs + (size_t)ch * SEQ + j4 * 4);
            }
            asm volatile("cp.async.commit_group;" ::: "memory");
        }

        // ---- S = QK^T : bf16 3-term, LDS.64 fragment pairs ----
        float sa[4][2][4];
#pragma unroll
        for (int mt = 0; mt < 4; mt++)
#pragma unroll
            for (int nt = 0; nt < 2; nt++)
#pragma unroll
                for (int c = 0; c < 4; c++) sa[mt][nt][c] = 0.0f;

#pragma unroll
        for (int kc = 0; kc < 2; kc++) {
            const int w0 = kc * 8;
            uint2 bh[2], bl[2];
#pragma unroll
            for (int nt = 0; nt < 2; nt++) {
                int key = nw * 16 + nt * 8 + g;
                int iw = key * 16 + ((w0 + 2 * l4) ^ ((key & 2) * 4));
                bh[nt] = *(const uint2*)(sKh + iw);
                bl[nt] = *(const uint2*)(sKl + iw);
            }
#pragma unroll
            for (int mt = 0; mt < 4; mt++) {
                int r0 = mw * 64 + mt * 16 + g;
                int iq0 = r0 * 16 + ((w0 + 2 * l4) ^ ((r0 & 2) * 4));
                uint2 qhA = *(const uint2*)(sQh + iq0);
                uint2 qhB = *(const uint2*)(sQh + iq0 + 128);
                uint2 qlA = *(const uint2*)(sQl + iq0);
                uint2 qlB = *(const uint2*)(sQl + iq0 + 128);
#pragma unroll
                for (int nt = 0; nt < 2; nt++) {
                    mma16(sa[mt][nt], qhA.x, qhB.x, qhA.y, qhB.y, bh[nt].x, bh[nt].y);
                    mma16(sa[mt][nt], qhA.x, qhB.x, qhA.y, qhB.y, bl[nt].x, bl[nt].y);
                    mma16(sa[mt][nt], qlA.x, qlB.x, qlA.y, qlB.y, bh[nt].x, bh[nt].y);
                }
            }
        }

        // ---- p = 2^s, truncate to tf32, store into interleaved P layout ----
#pragma unroll
        for (int mt = 0; mt < 4; mt++) {
            int r0 = mw * 64 + mt * 16 + g;
            float s0 = 0.0f, s1 = 0.0f;
#pragma unroll
            for (int nt = 0; nt < 2; nt++) {
                int col = nw * 16 + nt * 8 + l4 * 2;
                uint32_t e0 = __float_as_uint(ex2(sa[mt][nt][0])) & 0xFFFFE000u;
                uint32_t e1 = __float_as_uint(ex2(sa[mt][nt][1])) & 0xFFFFE000u;
                uint32_t e2 = __float_as_uint(ex2(sa[mt][nt][2])) & 0xFFFFE000u;
                uint32_t e3 = __float_as_uint(ex2(sa[mt][nt][3])) & 0xFFFFE000u;
                s0 += __uint_as_float(e0) + __uint_as_float(e1);
                s1 += __uint_as_float(e2) + __uint_as_float(e3);
                int ia = pPi(r0, col);
                int ib = pPi(r0, col + 1);
                sPu[ia] = e0;
                sPu[ib] = e1;
                sPu[ia + 512] = e2;   // (r0+8): same swizzle, +8*64
                sPu[ib + 512] = e3;
            }
            s0 += __shfl_xor_sync(0xffffffffu, s0, 1);
            s0 += __shfl_xor_sync(0xffffffffu, s0, 2);
            s1 += __shfl_xor_sync(0xffffffffu, s1, 1);
            s1 += __shfl_xor_sync(0xffffffffu, s1, 2);
            if (l4 == 0) {
                sLp[nw * 128 + r0] = s0;
                sLp[nw * 128 + r0 + 8] = s1;
            }
        }
        __syncthreads();   // sync1: sP/sLp visible; KT free

        if (have_next) {
            const char* kth_t = KThb + (size_t)(t + 1) * 4096;
            const char* ktl_t = KTlb + (size_t)(t + 1) * 4096;
            uint32_t off = (uint32_t)tid * 16u;
            cp_async16(sb + OFF_KTH + off, kth_t + off);
            cp_async16(sb + OFF_KTL + off, ktl_t + off);
            asm volatile("cp.async.commit_group;" ::: "memory");
        }
        if (tid < 128)
            sL[tid] += (sLp[tid] + sLp[128 + tid]) + (sLp[256 + tid] + sLp[384 + tid]);

        // ---- O += P @ V (tf32), all pairs via LDS.64 ----
        const uint32_t* sVb = sVu + (size_t)buf * 16384;
#pragma unroll
        for (int ks = 0; ks < 8; ks++) {
            const int k0 = ks * 8;
            uint2 paA[4], paB[4];
#pragma unroll
            for (int mt = 0; mt < 4; mt++) {
                int r0 = mw * 64 + mt * 16 + g;
                int ip = r0 * 64 + ((k0 + 2 * l4) ^ ((r0 & 3) * 8));
                paA[mt] = *(const uint2*)(sPu + ip);
                paB[mt] = *(const uint2*)(sPu + ip + 512);
            }
#pragma unroll
            for (int nt = 0; nt < 8; nt++) {
                int n = nw * 64 + nt * 8 + g;
                int iv = n * 64 + ((k0 + 2 * l4) ^ ((n & 3) * 8));
                uint2 bb = *(const uint2*)(sVb + iv);
#pragma unroll
                for (int mt = 0; mt < 4; mt++)
                    mma8(oa[mt][nt], paA[mt].x, paB[mt].x, paA[mt].y, paB[mt].y, bb.x, bb.y);
            }
        }

        asm volatile("cp.async.wait_group 0;" ::: "memory");
        __syncthreads();   // sync2
    }

    // ---- epilogue: O/l + residual ----
#pragma unroll
    for (int mt = 0; mt < 4; mt++) {
        int r0 = mw * 64 + mt * 16 + g;
        float inv0 = 1.0f / sL[r0];
        float inv1 = 1.0f / sL[r0 + 8];
        size_t row0 = (size_t)b * SEQ + q0 + r0;
#pragma unroll
        for (int nt = 0; nt < 8; nt++) {
            int col = nw * 64 + nt * 8 + l4 * 2;
            const float2* x0 = (const float2*)(X + (row0)*CDIM + col);
            const float2* x1 = (const float2*)(X + (row0 + 8) * CDIM + col);
            float2 xv0 = *x0, xv1 = *x1;
            float2 o0, o1;
            o0.x = oa[mt][nt][0] * inv0 + xv0.x;
            o0.y = oa[mt][nt][1] * inv0 + xv0.y;
            o1.x = oa[mt][nt][2] * inv1 + xv1.x;
            o1.y = oa[mt][nt][3] * inv1 + xv1.y;
            *(float2*)(Out + (row0)*CDIM + col) = o0;
            *(float2*)(Out + (row0 + 8) * CDIM + col) = o1;
        }
    }
}

// ============================================================================
// Merged projections: blocks [0,256) = V tf32-mma -> V^T interleaved gmem,
//                     blocks [256,512) = q/k FFMA2 (cp.async double-buffered).
// ============================================================================
#define PROJ_SMEM 65536
__device__ __forceinline__ int pA8(int r, int k) { return r * 32 + (k ^ ((r & 7) * 4)); }
__device__ __forceinline__ int pB8(int k, int n) { return k * 128 + (n ^ ((k & 3) * 8)); }

__global__ __launch_bounds__(256)
void proj_all(const float* __restrict__ Xg,
              const float* __restrict__ Wq, const float* __restrict__ bq,
              const float* __restrict__ Wk, const float* __restrict__ bk,
              const float* __restrict__ Wv, const float* __restrict__ bv,
              float* __restrict__ Yq, float* __restrict__ KTH, float* __restrict__ KTL,
              float* __restrict__ Vt) {
    extern __shared__ char smem[];
    const int tid = threadIdx.x;

    if (blockIdx.x < 256) {
        // ---------------- V projection (tf32 mma) -> V^T ----------------
        float* sA = (float*)smem;
        float* sB = (float*)(smem + 32768);
        const uint32_t sb = smem_u32(smem);
        const int lane = tid & 31;
        const int wid  = tid >> 5;
        const int mw   = wid & 1;
        const int nw   = wid >> 1;
        const int g    = lane >> 2;
        const int l4   = lane & 3;
        const int m0   = (blockIdx.x >> 1) * 128;
        const int n0   = (blockIdx.x & 1) * 128;

        float acc[4][4][4];
#pragma unroll
        for (int mt = 0; mt < 4; mt++)
#pragma unroll
            for (int nt = 0; nt < 4; nt++)
#pragma unroll
                for (int c = 0; c < 4; c++) acc[mt][nt][c] = 0.0f;

        auto load_tiles = [&](int k0, int bufsel) {
            uint32_t abase = sb + (uint32_t)bufsel * 16384u;
            uint32_t bbase = sb + 32768u + (uint32_t)bufsel * 16384u;
#pragma unroll
            for (int i = 0; i < 4; i++) {
                int idx = tid + i * 256;
                int r = idx >> 3, c4 = idx & 7;
                uint32_t dst = abase + (uint32_t)(r * 32 + ((c4 * 4) ^ ((r & 7) * 4))) * 4u;
                cp_async16(dst, Xg + (size_t)(m0 + r) * CDIM + k0 + c4 * 4);
            }
#pragma unroll
            for (int i = 0; i < 4; i++) {
                int idx = tid + i * 256;
                int k = idx >> 5, n4 = idx & 31;
                uint32_t dst = bbase + (uint32_t)(k * 128 + ((n4 * 4) ^ ((k & 3) * 8))) * 4u;
                cp_async16(dst, Wv + (size_t)(k0 + k) * CDIM + n0 + n4 * 4);
            }
            asm volatile("cp.async.commit_group;" ::: "memory");
        };

        load_tiles(0, 0);

#pragma unroll 1
        for (int t = 0; t < 8; t++) {
            const int buf = t & 1;
            const bool have_next = (t + 1 < 8);
            if (have_next) load_tiles((t + 1) * 32, 1 - buf);
            if (have_next) asm volatile("cp.async.wait_group 1;" ::: "memory");
            else           asm volatile("cp.async.wait_group 0;" ::: "memory");
            __syncthreads();

            const float* A = sA + (size_t)buf * 4096;
            const float* B = sB + (size_t)buf * 4096;
#pragma unroll
            for (int ks = 0; ks < 4; ks++) {
                const int k8 = ks * 8;
                uint32_t bfr[4][2];
#pragma unroll
                for (int nt = 0; nt < 4; nt++) {
                    int n = nw * 32 + nt * 8 + g;
                    bfr[nt][0] = __float_as_uint(B[pB8(k8 + l4, n)]);
                    bfr[nt][1] = __float_as_uint(B[pB8(k8 + 4 + l4, n)]);
                }
#pragma unroll
                for (int mt = 0; mt < 4; mt++) {
                    int r0 = mw * 64 + mt * 16 + g;
                    uint32_t a0 = __float_as_uint(A[pA8(r0, k8 + l4)]);
                    uint32_t a1 = __float_as_uint(A[pA8(r0 + 8, k8 + l4)]);
                    uint32_t a2 = __float_as_uint(A[pA8(r0, k8 + 4 + l4)]);
                    uint32_t a3 = __float_as_uint(A[pA8(r0 + 8, k8 + 4 + l4)]);
#pragma unroll
                    for (int nt = 0; nt < 4; nt++)
                        mma8(acc[mt][nt], a0, a1, a2, a3, bfr[nt][0], bfr[nt][1]);
                }
            }
            __syncthreads();
        }

        // epilogue: bias + scatter into V^T interleaved layout
#pragma unroll
        for (int mt = 0; mt < 4; mt++) {
            int key0 = m0 + mw * 64 + mt * 16 + g;       // global m
            int batch = key0 >> 12;
            int seq0 = key0 & 4095;
            size_t vb = (size_t)batch * CDIM * SEQ;
            int t0 = seq0 & ~63;
            int i0 = intl8b(seq0 & 63);
            int i1 = intl8b((seq0 & 63) + 8);
#pragma unroll
            for (int nt = 0; nt < 4; nt++) {
                int col = n0 + nw * 32 + nt * 8 + l4 * 2;
                float2 bb = *(const float2*)(bv + col);
                Vt[vb + (size_t)col * SEQ + t0 + i0]       = acc[mt][nt][0] + bb.x;
                Vt[vb + (size_t)(col + 1) * SEQ + t0 + i0] = acc[mt][nt][1] + bb.y;
                Vt[vb + (size_t)col * SEQ + t0 + i1]       = acc[mt][nt][2] + bb.x;
                Vt[vb + (size_t)(col + 1) * SEQ + t0 + i1] = acc[mt][nt][3] + bb.y;
            }
        }
    } else {
        // ---------------- q/k projection (FFMA2, cp.async double-buffered) ----------------
        constexpr int TM = 2, TN = 4, TX = 8;
        float* As  = (float*)smem;                 // 2 x [64][20]
        float* Bqs = As + 2 * 64 * 20;             // 2 x [16][32]
        float* Bks = Bqs + 2 * 512;
        const uint32_t sbq = smem_u32(smem);
        const uint32_t bq_off = (uint32_t)(2 * 64 * 20) * 4u;
        const uint32_t bk_off = bq_off + 2 * 512 * 4u;
        const int tx = tid % TX, ty = tid / TX;
        const int m0 = (blockIdx.x - 256) * 64;

        unsigned long long aq[TM][2], ak[TM][2];
#pragma unroll
        for (int i = 0; i < TM; i++) {
            aq[i][0] = aq[i][1] = 0ull;
            ak[i][0] = ak[i][1] = 0ull;
        }

        auto loadqk = [&](int k0, int bufsel) {
            {
                int m = tid >> 2, kq = tid & 3;
                cp_async16(sbq + (uint32_t)(bufsel * 1280 + m * 20 + kq * 4) * 4u,
                           Xg + (size_t)(m0 + m) * CDIM + k0 + kq * 4);
            }
            if (tid < 128) {
                int kk = tid >> 3, nq = tid & 7;
                cp_async16(sbq + bq_off + (uint32_t)(bufsel * 512 + kk * 32 + nq * 4) * 4u,
                           Wq + (size_t)(k0 + kk) * DDIM + nq * 4);
            } else {
                int t2 = tid - 128;
                int kk = t2 >> 3, nq = t2 & 7;
                cp_async16(sbq + bk_off + (uint32_t)(bufsel * 512 + kk * 32 + nq * 4) * 4u,
                           Wk + (size_t)(k0 + kk) * DDIM + nq * 4);
            }
            asm volatile("cp.async.commit_group;" ::: "memory");
        };

        loadqk(0, 0);

#pragma unroll 1
        for (int kt = 0; kt < 16; kt++) {
            const int buf = kt & 1;
            asm volatile("cp.async.wait_group 0;" ::: "memory");
            __syncthreads();
            if (kt < 15) loadqk((kt + 1) * 16, 1 - buf);

            const float* Af = As + buf * 1280;
            const float* Bqf = Bqs + buf * 512;
            const float* Bkf = Bks + buf * 512;
#pragma unroll
            for (int kk = 0; kk < 16; kk++) {
                ulonglong2 bbq = *(const ulonglong2*)&Bqf[kk * 32 + tx * TN];
                ulonglong2 bbk = *(const ulonglong2*)&Bkf[kk * 32 + tx * TN];
#pragma unroll
                for (int i = 0; i < TM; i++) {
                    float a = Af[(ty * TM + i) * 20 + kk];
                    unsigned long long a2 = pack2(a, a);
                    aq[i][0] = ffma2(bbq.x, a2, aq[i][0]);
                    aq[i][1] = ffma2(bbq.y, a2, aq[i][1]);
                    ak[i][0] = ffma2(bbk.x, a2, ak[i][0]);
                    ak[i][1] = ffma2(bbk.y, a2, ak[i][1]);
                }
            }
        }
        float4 bq4 = *(const float4*)(bq + tx * TN);
        float4 bk4 = *(const float4*)(bk + tx * TN);
#pragma unroll
        for (int i = 0; i < TM; i++) {
            int m = m0 + ty * TM + i;
            float v0, v1, v2, v3;
            unpack2(aq[i][0], v0, v1);
            unpack2(aq[i][1], v2, v3);
            float4 o;
            o.x = v0 + bq4.x; o.y = v1 + bq4.y; o.z = v2 + bq4.z; o.w = v3 + bq4.w;
            *(float4*)(Yq + (size_t)m * DDIM + tx * TN) = o;
            // k: bf16 hi/lo split into interleaved KT tile layout
            float kv[4];
            unpack2(ak[i][0], kv[0], kv[1]);
            unpack2(ak[i][1], kv[2], kv[3]);
            kv[0] += bk4.x; kv[1] += bk4.y; kv[2] += bk4.z; kv[3] += bk4.w;
            int key = m & 63;
            size_t base = (size_t)(m >> 6) * 1024;
            uint32_t hi0 = bftruncpack(kv[0], kv[1]);
            uint32_t hi1 = bftruncpack(kv[2], kv[3]);
            uint32_t lo0 = bfpack(bftrunc_res(kv[0]), bftrunc_res(kv[1]));
            uint32_t lo1 = bfpack(bftrunc_res(kv[2]), bftrunc_res(kv[3]));
            int w0 = pK16i(key, 2 * tx);
            int w1 = pK16i(key, 2 * tx + 1);
            ((uint32_t*)KTH)[base + w0] = hi0;
            ((uint32_t*)KTH)[base + w1] = hi1;
            ((uint32_t*)KTL)[base + w0] = lo0;
            ((uint32_t*)KTL)[base + w1] = lo1;
        }
    }
}

// ============================================================================
extern "C" void kernel_launch(void* const* d_in, const int* in_sizes, int n_in,
                              void* d_out, int out_size) {
    const float* x  = (const float*)d_in[0];
    const float* wq = (const float*)d_in[1];
    const float* bq = (const float*)d_in[2];
    const float* wk = (const float*)d_in[3];
    const float* bk = (const float*)d_in[4];
    const float* wv = (const float*)d_in[5];
    const float* bv = (const float*)d_in[6];
    float* out = (float*)d_out;

    float *qp, *kthp, *ktlp, *vtp;
    cudaGetSymbolAddress((void**)&qp, g_q);
    cudaGetSymbolAddress((void**)&kthp, g_kth);
    cudaGetSymbolAddress((void**)&ktlp, g_ktl);
    cudaGetSymbolAddress((void**)&vtp, g_vt);

    {
        cudaFuncSetAttribute(proj_all, cudaFuncAttributeMaxDynamicSharedMemorySize, PROJ_SMEM);
        proj_all<<<512, 256, PROJ_SMEM>>>(x, wq, bq, wk, bk, wv, bv, qp, kthp, ktlp, vtp);
    }
    {
        cudaFuncSetAttribute(flash_mma, cudaFuncAttributeMaxDynamicSharedMemorySize, FLASH_SMEM);
        dim3 g(SEQ / TQ, BATCH);
        flash_mma<<<g, 256, FLASH_SMEM>>>(qp, kthp, ktlp, vtp, x, out);
    }
}

// round 14
// speedup vs baseline: 1.1004x; 1.1004x over previous
#include <cuda_runtime.h>
#include <cstdint>

#define BATCH 4
#define SEQ   4096
#define CDIM  256
#define DDIM  32
#define TQ    128
#define TK    64
#define NT_TILES (SEQ / TK)
#define LOG2E 1.4426950408889634f

// ---- scratch ----
__device__ float g_q[BATCH * SEQ * DDIM];
__device__ float g_kth[BATCH * NT_TILES * 1024];   // K-hi bf16x2 words, KT tile layout
__device__ float g_ktl[BATCH * NT_TILES * 1024];   // K-lo bf16x2 words
__device__ float g_v[BATCH * SEQ * CDIM];

// ---- helpers ----
__device__ __forceinline__ unsigned long long pack2(float lo, float hi) {
    unsigned long long r;
    asm("mov.b64 %0, {%1, %2};" : "=l"(r) : "f"(lo), "f"(hi));
    return r;
}
__device__ __forceinline__ void unpack2(unsigned long long v, float& lo, float& hi) {
    asm("mov.b64 {%0, %1}, %2;" : "=f"(lo), "=f"(hi) : "l"(v));
}
__device__ __forceinline__ unsigned long long ffma2(unsigned long long a, unsigned long long b,
                                                    unsigned long long c) {
    unsigned long long d;
    asm("fma.rn.f32x2 %0, %1, %2, %3;" : "=l"(d) : "l"(a), "l"(b), "l"(c));
    return d;
}
__device__ __forceinline__ uint32_t smem_u32(const void* p) {
    uint32_t a;
    asm("{ .reg .u64 t; cvta.to.shared.u64 t, %1; cvt.u32.u64 %0, t; }" : "=r"(a) : "l"(p));
    return a;
}
__device__ __forceinline__ void cp_async16(uint32_t dst, const void* src) {
    asm volatile("cp.async.cg.shared.global [%0], [%1], 16;" :: "r"(dst), "l"(src));
}
__device__ __forceinline__ float ex2(float x) {
    float r;
    asm("ex2.approx.f32 %0, %1;" : "=f"(r) : "f"(x));
    return r;
}
__device__ __forceinline__ uint32_t bfpack(float lo, float hi) {
    uint32_t r;
    asm("cvt.rn.bf16x2.f32 %0, %1, %2;" : "=r"(r) : "f"(hi), "f"(lo));
    return r;
}
__device__ __forceinline__ uint32_t bftruncpack(float x0, float x1) {
    return __byte_perm(__float_as_uint(x0), __float_as_uint(x1), 0x7632);
}
__device__ __forceinline__ float bftrunc_res(float x) {
    return x - __uint_as_float(__float_as_uint(x) & 0xFFFF0000u);
}
__device__ __forceinline__ void mma8(float d[4], uint32_t a0, uint32_t a1, uint32_t a2,
                                     uint32_t a3, uint32_t b0, uint32_t b1) {
    asm volatile(
        "mma.sync.aligned.m16n8k8.row.col.f32.tf32.tf32.f32 "
        "{%0,%1,%2,%3}, {%4,%5,%6,%7}, {%8,%9}, {%0,%1,%2,%3};"
        : "+f"(d[0]), "+f"(d[1]), "+f"(d[2]), "+f"(d[3])
        : "r"(a0), "r"(a1), "r"(a2), "r"(a3), "r"(b0), "r"(b1));
}
__device__ __forceinline__ void mma16(float d[4], uint32_t a0, uint32_t a1, uint32_t a2,
                                      uint32_t a3, uint32_t b0, uint32_t b1) {
    asm volatile(
        "mma.sync.aligned.m16n8k16.row.col.f32.bf16.bf16.f32 "
        "{%0,%1,%2,%3}, {%4,%5,%6,%7}, {%8,%9}, {%0,%1,%2,%3};"
        : "+f"(d[0]), "+f"(d[1]), "+f"(d[2]), "+f"(d[3])
        : "r"(a0), "r"(a1), "r"(a2), "r"(a3), "r"(b0), "r"(b1));
}

// ---- flash smem byte offsets (round-12, proven 257 us) ----
#define OFF_QH16 0          /* 8 KB */
#define OFF_QL16 8192       /* 8 KB */
#define OFF_KTH  16384      /* 4 KB */
#define OFF_KTL  20480      /* 4 KB */
#define OFF_P    24576      /* 32 KB */
#define OFF_V    57344      /* 2 x 64 KB */
#define OFF_L    188416
#define OFF_LP   188928
#define FLASH_SMEM 190976

// round-12 word-index swizzles (proven)
__device__ __forceinline__ int pQ16(int r, int w)   { return r * 16 + (w ^ ((r & 7) * 2)); }
__device__ __forceinline__ int pK16(int key, int w) { return key * 16 + (w ^ ((key & 7) * 2)); }
__device__ __forceinline__ int pP(int r, int c)     { return r * 64 + (c ^ ((r & 7) * 4)); }
__device__ __forceinline__ int pV(int k, int n)     { return k * 256 + (n ^ ((k & 3) * 8)); }

// ============================================================================
// Flash attention (round-12 verbatim): bf16 3-term QK, tf32 PV.
// 256 threads = 8 warps: mw = wid&1 (64 rows), nw = wid>>1 (16 keys / 64 PV cols)
// ============================================================================
__global__ __launch_bounds__(256, 1)
void flash_mma(const float* __restrict__ Qg,
               const float* __restrict__ KTHg, const float* __restrict__ KTLg,
               const float* __restrict__ Vg, const float* __restrict__ X,
               float* __restrict__ Out) {
    extern __shared__ char smem[];
    uint32_t* sQh = (uint32_t*)(smem + OFF_QH16);
    uint32_t* sQl = (uint32_t*)(smem + OFF_QL16);
    uint32_t* sKh = (uint32_t*)(smem + OFF_KTH);
    uint32_t* sKl = (uint32_t*)(smem + OFF_KTL);
    uint32_t* sPu = (uint32_t*)(smem + OFF_P);
    uint32_t* sVu = (uint32_t*)(smem + OFF_V);
    float*    sL  = (float*)(smem + OFF_L);
    float*    sLp = (float*)(smem + OFF_LP);
    const uint32_t sb = smem_u32(smem);

    const int tid  = threadIdx.x;
    const int lane = tid & 31;
    const int wid  = tid >> 5;
    const int mw   = wid & 1;
    const int nw   = wid >> 1;
    const int g    = lane >> 2;
    const int l4   = lane & 3;
    const int b    = blockIdx.y;
    const int q0   = blockIdx.x * TQ;

    const float* Qb = Qg + ((size_t)b * SEQ + q0) * DDIM;
    const char*  KThb = (const char*)(KTHg + (size_t)b * NT_TILES * 1024);
    const char*  KTlb = (const char*)(KTLg + (size_t)b * NT_TILES * 1024);
    const float* Vb = Vg + (size_t)b * SEQ * CDIM;

    // ---- prologue ----
    if (tid < 128) sL[tid] = 0.0f;
#pragma unroll
    for (int i = 0; i < 4; i++) {
        int idx = tid + i * 256;
        int r = idx >> 3, d4 = idx & 7;
        float4 v = *(const float4*)(Qb + r * DDIM + d4 * 4);
        v.x *= LOG2E; v.y *= LOG2E; v.z *= LOG2E; v.w *= LOG2E;
        uint32_t hi0 = bftruncpack(v.x, v.y);
        uint32_t hi1 = bftruncpack(v.z, v.w);
        uint32_t lo0 = bfpack(bftrunc_res(v.x), bftrunc_res(v.y));
        uint32_t lo1 = bfpack(bftrunc_res(v.z), bftrunc_res(v.w));
        sQh[pQ16(r, 2 * d4)]     = hi0;
        sQh[pQ16(r, 2 * d4 + 1)] = hi1;
        sQl[pQ16(r, 2 * d4)]     = lo0;
        sQl[pQ16(r, 2 * d4 + 1)] = lo1;
    }
    {
        uint32_t off = (uint32_t)tid * 16u;
        cp_async16(sb + OFF_KTH + off, KThb + off);
        cp_async16(sb + OFF_KTL + off, KTlb + off);
    }
#pragma unroll
    for (int i = 0; i < 16; i++) {
        int f = tid + i * 256;
        int key = f >> 6, n4 = f & 63;
        uint32_t dst = sb + OFF_V + (uint32_t)pV(key, n4 * 4) * 4u;
        cp_async16(dst, Vb + (size_t)key * CDIM + n4 * 4);
    }
    asm volatile("cp.async.commit_group;" ::: "memory");
    asm volatile("cp.async.wait_group 0;" ::: "memory");
    __syncthreads();

    float oa[4][8][4];
#pragma unroll
    for (int mt = 0; mt < 4; mt++)
#pragma unroll
        for (int nt = 0; nt < 8; nt++)
#pragma unroll
            for (int c = 0; c < 4; c++) oa[mt][nt][c] = 0.0f;

#pragma unroll 1
    for (int t = 0; t < NT_TILES; t++) {
        const int buf = t & 1;
        const bool have_next = (t + 1 < NT_TILES);

        if (have_next) {
            const float* Vs = Vb + (size_t)(t + 1) * TK * CDIM;
            uint32_t vb0 = sb + OFF_V + (uint32_t)(1 - buf) * 65536u;
#pragma unroll
            for (int i = 0; i < 16; i++) {
                int f = tid + i * 256;
                int key = f >> 6, n4 = f & 63;
                cp_async16(vb0 + (uint32_t)pV(key, n4 * 4) * 4u, Vs + (size_t)key * CDIM + n4 * 4);
            }
            asm volatile("cp.async.commit_group;" ::: "memory");
        }

        // ---- S = QK^T : bf16 3-term ----
        float sa[4][2][4];
#pragma unroll
        for (int mt = 0; mt < 4; mt++)
#pragma unroll
            for (int nt = 0; nt < 2; nt++)
#pragma unroll
                for (int c = 0; c < 4; c++) sa[mt][nt][c] = 0.0f;

#pragma unroll
        for (int kc = 0; kc < 2; kc++) {
            const int w0 = kc * 8;
            uint32_t bh[2][2], bl[2][2];
#pragma unroll
            for (int nt = 0; nt < 2; nt++) {
                int key = nw * 16 + nt * 8 + g;
                bh[nt][0] = sKh[pK16(key, w0 + l4)];
                bh[nt][1] = sKh[pK16(key, w0 + 4 + l4)];
                bl[nt][0] = sKl[pK16(key, w0 + l4)];
                bl[nt][1] = sKl[pK16(key, w0 + 4 + l4)];
            }
#pragma unroll
            for (int mt = 0; mt < 4; mt++) {
                int r0 = mw * 64 + mt * 16 + g;
                uint32_t qh0 = sQh[pQ16(r0, w0 + l4)];
                uint32_t qh1 = sQh[pQ16(r0 + 8, w0 + l4)];
                uint32_t qh2 = sQh[pQ16(r0, w0 + 4 + l4)];
                uint32_t qh3 = sQh[pQ16(r0 + 8, w0 + 4 + l4)];
                uint32_t ql0 = sQl[pQ16(r0, w0 + l4)];
                uint32_t ql1 = sQl[pQ16(r0 + 8, w0 + l4)];
                uint32_t ql2 = sQl[pQ16(r0, w0 + 4 + l4)];
                uint32_t ql3 = sQl[pQ16(r0 + 8, w0 + 4 + l4)];
#pragma unroll
                for (int nt = 0; nt < 2; nt++) {
                    mma16(sa[mt][nt], qh0, qh1, qh2, qh3, bh[nt][0], bh[nt][1]);
                    mma16(sa[mt][nt], qh0, qh1, qh2, qh3, bl[nt][0], bl[nt][1]);
                    mma16(sa[mt][nt], ql0, ql1, ql2, ql3, bh[nt][0], bh[nt][1]);
                }
            }
        }

        // ---- p = 2^s, truncate to tf32, STS.64 pairs, partial sums ----
#pragma unroll
        for (int mt = 0; mt < 4; mt++) {
            int r0 = mw * 64 + mt * 16 + g;
            float s0 = 0.0f, s1 = 0.0f;
#pragma unroll
            for (int nt = 0; nt < 2; nt++) {
                int col = nw * 16 + nt * 8 + l4 * 2;
                uint32_t e0 = __float_as_uint(ex2(sa[mt][nt][0])) & 0xFFFFE000u;
                uint32_t e1 = __float_as_uint(ex2(sa[mt][nt][1])) & 0xFFFFE000u;
                uint32_t e2 = __float_as_uint(ex2(sa[mt][nt][2])) & 0xFFFFE000u;
                uint32_t e3 = __float_as_uint(ex2(sa[mt][nt][3])) & 0xFFFFE000u;
                s0 += __uint_as_float(e0) + __uint_as_float(e1);
                s1 += __uint_as_float(e2) + __uint_as_float(e3);
                uint2 w0p; w0p.x = e0; w0p.y = e1;
                uint2 w1p; w1p.x = e2; w1p.y = e3;
                *(uint2*)(sPu + pP(r0, col)) = w0p;
                *(uint2*)(sPu + pP(r0 + 8, col)) = w1p;
            }
            s0 += __shfl_xor_sync(0xffffffffu, s0, 1);
            s0 += __shfl_xor_sync(0xffffffffu, s0, 2);
            s1 += __shfl_xor_sync(0xffffffffu, s1, 1);
            s1 += __shfl_xor_sync(0xffffffffu, s1, 2);
            if (l4 == 0) {
                sLp[nw * 128 + r0] = s0;
                sLp[nw * 128 + r0 + 8] = s1;
            }
        }
        __syncthreads();   // sync1

        if (have_next) {
            const char* kth_t = KThb + (size_t)(t + 1) * 4096;
            const char* ktl_t = KTlb + (size_t)(t + 1) * 4096;
            uint32_t off = (uint32_t)tid * 16u;
            cp_async16(sb + OFF_KTH + off, kth_t + off);
            cp_async16(sb + OFF_KTL + off, ktl_t + off);
            asm volatile("cp.async.commit_group;" ::: "memory");
        }
        if (tid < 128)
            sL[tid] += (sLp[tid] + sLp[128 + tid]) + (sLp[256 + tid] + sLp[384 + tid]);

        // ---- O += P @ V (tf32) ----
        const uint32_t* sVb = sVu + (size_t)buf * 16384;
#pragma unroll
        for (int ks = 0; ks < 8; ks++) {
            const int k0 = ks * 8;
            uint32_t pa[4][4];
#pragma unroll
            for (int mt = 0; mt < 4; mt++) {
                int r0 = mw * 64 + mt * 16 + g;
                pa[mt][0] = sPu[pP(r0, k0 + l4)];
                pa[mt][1] = sPu[pP(r0 + 8, k0 + l4)];
                pa[mt][2] = sPu[pP(r0, k0 + 4 + l4)];
                pa[mt][3] = sPu[pP(r0 + 8, k0 + 4 + l4)];
            }
#pragma unroll
            for (int nt = 0; nt < 8; nt++) {
                int n = nw * 64 + nt * 8 + g;
                uint32_t b0 = sVb[pV(k0 + l4, n)];
                uint32_t b1 = sVb[pV(k0 + 4 + l4, n)];
#pragma unroll
                for (int mt = 0; mt < 4; mt++)
                    mma8(oa[mt][nt], pa[mt][0], pa[mt][1], pa[mt][2], pa[mt][3], b0, b1);
            }
        }

        asm volatile("cp.async.wait_group 0;" ::: "memory");
        __syncthreads();   // sync2
    }

    // ---- epilogue: O/l + residual ----
#pragma unroll
    for (int mt = 0; mt < 4; mt++) {
        int r0 = mw * 64 + mt * 16 + g;
        float inv0 = 1.0f / sL[r0];
        float inv1 = 1.0f / sL[r0 + 8];
        size_t row0 = (size_t)b * SEQ + q0 + r0;
#pragma unroll
        for (int nt = 0; nt < 8; nt++) {
            int col = nw * 64 + nt * 8 + l4 * 2;
            const float2* x0 = (const float2*)(X + (row0)*CDIM + col);
            const float2* x1 = (const float2*)(X + (row0 + 8) * CDIM + col);
            float2 xv0 = *x0, xv1 = *x1;
            float2 o0, o1;
            o0.x = oa[mt][nt][0] * inv0 + xv0.x;
            o0.y = oa[mt][nt][1] * inv0 + xv0.y;
            o1.x = oa[mt][nt][2] * inv1 + xv1.x;
            o1.y = oa[mt][nt][3] * inv1 + xv1.y;
            *(float2*)(Out + (row0)*CDIM + col) = o0;
            *(float2*)(Out + (row0 + 8) * CDIM + col) = o1;
        }
    }
}

// ============================================================================
// Merged projections: blocks [0,256) = V tf32-mma (round-12 branch),
//                     blocks [256,512) = q/k FFMA2, cp.async double-buffered
//                     (round-13 branch).
// ============================================================================
#define PROJ_SMEM 65536
__device__ __forceinline__ int pA8(int r, int k) { return r * 32 + (k ^ ((r & 7) * 4)); }
__device__ __forceinline__ int pB8(int k, int n) { return k * 128 + (n ^ ((k & 3) * 8)); }

__global__ __launch_bounds__(256)
void proj_all(const float* __restrict__ Xg,
              const float* __restrict__ Wq, const float* __restrict__ bq,
              const float* __restrict__ Wk, const float* __restrict__ bk,
              const float* __restrict__ Wv, const float* __restrict__ bv,
              float* __restrict__ Yq, float* __restrict__ KTH, float* __restrict__ KTL,
              float* __restrict__ Vout) {
    extern __shared__ char smem[];
    const int tid = threadIdx.x;

    if (blockIdx.x < 256) {
        // ---------------- V projection (tf32 mma), plain V layout ----------------
        float* sA = (float*)smem;
        float* sB = (float*)(smem + 32768);
        const uint32_t sb = smem_u32(smem);
        const int lane = tid & 31;
        const int wid  = tid >> 5;
        const int mw   = wid & 1;
        const int nw   = wid >> 1;
        const int g    = lane >> 2;
        const int l4   = lane & 3;
        const int m0   = (blockIdx.x >> 1) * 128;
        const int n0   = (blockIdx.x & 1) * 128;

        float acc[4][4][4];
#pragma unroll
        for (int mt = 0; mt < 4; mt++)
#pragma unroll
            for (int nt = 0; nt < 4; nt++)
#pragma unroll
                for (int c = 0; c < 4; c++) acc[mt][nt][c] = 0.0f;

        auto load_tiles = [&](int k0, int bufsel) {
            uint32_t abase = sb + (uint32_t)bufsel * 16384u;
            uint32_t bbase = sb + 32768u + (uint32_t)bufsel * 16384u;
#pragma unroll
            for (int i = 0; i < 4; i++) {
                int idx = tid + i * 256;
                int r = idx >> 3, c4 = idx & 7;
                uint32_t dst = abase + (uint32_t)(r * 32 + ((c4 * 4) ^ ((r & 7) * 4))) * 4u;
                cp_async16(dst, Xg + (size_t)(m0 + r) * CDIM + k0 + c4 * 4);
            }
#pragma unroll
            for (int i = 0; i < 4; i++) {
                int idx = tid + i * 256;
                int k = idx >> 5, n4 = idx & 31;
                uint32_t dst = bbase + (uint32_t)(k * 128 + ((n4 * 4) ^ ((k & 3) * 8))) * 4u;
                cp_async16(dst, Wv + (size_t)(k0 + k) * CDIM + n0 + n4 * 4);
            }
            asm volatile("cp.async.commit_group;" ::: "memory");
        };

        load_tiles(0, 0);

#pragma unroll 1
        for (int t = 0; t < 8; t++) {
            const int buf = t & 1;
            const bool have_next = (t + 1 < 8);
            if (have_next) load_tiles((t + 1) * 32, 1 - buf);
            if (have_next) asm volatile("cp.async.wait_group 1;" ::: "memory");
            else           asm volatile("cp.async.wait_group 0;" ::: "memory");
            __syncthreads();

            const float* A = sA + (size_t)buf * 4096;
            const float* B = sB + (size_t)buf * 4096;
#pragma unroll
            for (int ks = 0; ks < 4; ks++) {
                const int k8 = ks * 8;
                uint32_t bfr[4][2];
#pragma unroll
                for (int nt = 0; nt < 4; nt++) {
                    int n = nw * 32 + nt * 8 + g;
                    bfr[nt][0] = __float_as_uint(B[pB8(k8 + l4, n)]);
                    bfr[nt][1] = __float_as_uint(B[pB8(k8 + 4 + l4, n)]);
                }
#pragma unroll
                for (int mt = 0; mt < 4; mt++) {
                    int r0 = mw * 64 + mt * 16 + g;
                    uint32_t a0 = __float_as_uint(A[pA8(r0, k8 + l4)]);
                    uint32_t a1 = __float_as_uint(A[pA8(r0 + 8, k8 + l4)]);
                    uint32_t a2 = __float_as_uint(A[pA8(r0, k8 + 4 + l4)]);
                    uint32_t a3 = __float_as_uint(A[pA8(r0 + 8, k8 + 4 + l4)]);
#pragma unroll
                    for (int nt = 0; nt < 4; nt++)
                        mma8(acc[mt][nt], a0, a1, a2, a3, bfr[nt][0], bfr[nt][1]);
                }
            }
            __syncthreads();
        }

#pragma unroll
        for (int mt = 0; mt < 4; mt++) {
            int r0 = m0 + mw * 64 + mt * 16 + g;
#pragma unroll
            for (int nt = 0; nt < 4; nt++) {
                int col = n0 + nw * 32 + nt * 8 + l4 * 2;
                float2 bb = *(const float2*)(bv + col);
                float2 o0, o1;
                o0.x = acc[mt][nt][0] + bb.x;
                o0.y = acc[mt][nt][1] + bb.y;
                o1.x = acc[mt][nt][2] + bb.x;
                o1.y = acc[mt][nt][3] + bb.y;
                *(float2*)(Vout + (size_t)r0 * CDIM + col) = o0;
                *(float2*)(Vout + (size_t)(r0 + 8) * CDIM + col) = o1;
            }
        }
    } else {
        // ---------------- q/k projection (FFMA2, cp.async double-buffered) ----------------
        constexpr int TM = 2, TN = 4, TX = 8;
        float* As  = (float*)smem;                 // 2 x [64][20]
        float* Bqs = As + 2 * 64 * 20;             // 2 x [16][32]
        float* Bks = Bqs + 2 * 512;
        const uint32_t sbq = smem_u32(smem);
        const uint32_t bq_off = (uint32_t)(2 * 64 * 20) * 4u;
        const uint32_t bk_off = bq_off + 2 * 512 * 4u;
        const int tx = tid % TX, ty = tid / TX;
        const int m0 = (blockIdx.x - 256) * 64;

        unsigned long long aq[TM][2], ak[TM][2];
#pragma unroll
        for (int i = 0; i < TM; i++) {
            aq[i][0] = aq[i][1] = 0ull;
            ak[i][0] = ak[i][1] = 0ull;
        }

        auto loadqk = [&](int k0, int bufsel) {
            {
                int m = tid >> 2, kq = tid & 3;
                cp_async16(sbq + (uint32_t)(bufsel * 1280 + m * 20 + kq * 4) * 4u,
                           Xg + (size_t)(m0 + m) * CDIM + k0 + kq * 4);
            }
            if (tid < 128) {
                int kk = tid >> 3, nq = tid & 7;
                cp_async16(sbq + bq_off + (uint32_t)(bufsel * 512 + kk * 32 + nq * 4) * 4u,
                           Wq + (size_t)(k0 + kk) * DDIM + nq * 4);
            } else {
                int t2 = tid - 128;
                int kk = t2 >> 3, nq = t2 & 7;
                cp_async16(sbq + bk_off + (uint32_t)(bufsel * 512 + kk * 32 + nq * 4) * 4u,
                           Wk + (size_t)(k0 + kk) * DDIM + nq * 4);
            }
            asm volatile("cp.async.commit_group;" ::: "memory");
        };

        loadqk(0, 0);

#pragma unroll 1
        for (int kt = 0; kt < 16; kt++) {
            const int buf = kt & 1;
            asm volatile("cp.async.wait_group 0;" ::: "memory");
            __syncthreads();
            if (kt < 15) loadqk((kt + 1) * 16, 1 - buf);

            const float* Af = As + buf * 1280;
            const float* Bqf = Bqs + buf * 512;
            const float* Bkf = Bks + buf * 512;
#pragma unroll
            for (int kk = 0; kk < 16; kk++) {
                ulonglong2 bbq = *(const ulonglong2*)&Bqf[kk * 32 + tx * TN];
                ulonglong2 bbk = *(const ulonglong2*)&Bkf[kk * 32 + tx * TN];
#pragma unroll
                for (int i = 0; i < TM; i++) {
                    float a = Af[(ty * TM + i) * 20 + kk];
                    unsigned long long a2 = pack2(a, a);
                    aq[i][0] = ffma2(bbq.x, a2, aq[i][0]);
                    aq[i][1] = ffma2(bbq.y, a2, aq[i][1]);
                    ak[i][0] = ffma2(bbk.x, a2, ak[i][0]);
                    ak[i][1] = ffma2(bbk.y, a2, ak[i][1]);
                }
            }
        }
        float4 bq4 = *(const float4*)(bq + tx * TN);
        float4 bk4 = *(const float4*)(bk + tx * TN);
#pragma unroll
        for (int i = 0; i < TM; i++) {
            int m = m0 + ty * TM + i;
            float v0, v1, v2, v3;
            unpack2(aq[i][0], v0, v1);
            unpack2(aq[i][1], v2, v3);
            float4 o;
            o.x = v0 + bq4.x; o.y = v1 + bq4.y; o.z = v2 + bq4.z; o.w = v3 + bq4.w;
            *(float4*)(Yq + (size_t)m * DDIM + tx * TN) = o;
            // k: bf16 hi/lo split into KT tile layout (round-12 pK16)
            float kv[4];
            unpack2(ak[i][0], kv[0], kv[1]);
            unpack2(ak[i][1], kv[2], kv[3]);
            kv[0] += bk4.x; kv[1] += bk4.y; kv[2] += bk4.z; kv[3] += bk4.w;
            int key = m & 63;
            size_t base = (size_t)(m >> 6) * 1024;
            uint32_t hi0 = bftruncpack(kv[0], kv[1]);
            uint32_t hi1 = bftruncpack(kv[2], kv[3]);
            uint32_t lo0 = bfpack(bftrunc_res(kv[0]), bftrunc_res(kv[1]));
            uint32_t lo1 = bfpack(bftrunc_res(kv[2]), bftrunc_res(kv[3]));
            int w0 = pK16(key, 2 * tx);
            int w1 = pK16(key, 2 * tx + 1);
            ((uint32_t*)KTH)[base + w0] = hi0;
            ((uint32_t*)KTH)[base + w1] = hi1;
            ((uint32_t*)KTL)[base + w0] = lo0;
            ((uint32_t*)KTL)[base + w1] = lo1;
        }
    }
}

// ============================================================================
extern "C" void kernel_launch(void* const* d_in, const int* in_sizes, int n_in,
                              void* d_out, int out_size) {
    const float* x  = (const float*)d_in[0];
    const float* wq = (const float*)d_in[1];
    const float* bq = (const float*)d_in[2];
    const float* wk = (const float*)d_in[3];
    const float* bk = (const float*)d_in[4];
    const float* wv = (const float*)d_in[5];
    const float* bv = (const float*)d_in[6];
    float* out = (float*)d_out;

    float *qp, *kthp, *ktlp, *vp;
    cudaGetSymbolAddress((void**)&qp, g_q);
    cudaGetSymbolAddress((void**)&kthp, g_kth);
    cudaGetSymbolAddress((void**)&ktlp, g_ktl);
    cudaGetSymbolAddress((void**)&vp, g_v);

    {
        cudaFuncSetAttribute(proj_all, cudaFuncAttributeMaxDynamicSharedMemorySize, PROJ_SMEM);
        proj_all<<<512, 256, PROJ_SMEM>>>(x, wq, bq, wk, bk, wv, bv, qp, kthp, ktlp, vp);
    }
    {
        cudaFuncSetAttribute(flash_mma, cudaFuncAttributeMaxDynamicSharedMemorySize, FLASH_SMEM);
        dim3 g(SEQ / TQ, BATCH);
        flash_mma<<<g, 256, FLASH_SMEM>>>(qp, kthp, ktlp, vp, x, out);
    }
}

// round 15
// speedup vs baseline: 1.1400x; 1.0359x over previous
#include <cuda_runtime.h>
#include <cstdint>

#define BATCH 4
#define SEQ   4096
#define CDIM  256
#define DDIM  32
#define TQ    128
#define TK    64
#define NT_TILES (SEQ / TK)
#define LOG2E 1.4426950408889634f

// ---- scratch ----
__device__ float g_q[BATCH * SEQ * DDIM];
__device__ float g_kth[BATCH * NT_TILES * 1024];   // K-hi bf16x2 words, KT tile layout
__device__ float g_ktl[BATCH * NT_TILES * 1024];   // K-lo bf16x2 words
__device__ float g_v[BATCH * SEQ * CDIM];

// ---- helpers ----
__device__ __forceinline__ uint32_t smem_u32(const void* p) {
    uint32_t a;
    asm("{ .reg .u64 t; cvta.to.shared.u64 t, %1; cvt.u32.u64 %0, t; }" : "=r"(a) : "l"(p));
    return a;
}
__device__ __forceinline__ void cp_async16(uint32_t dst, const void* src) {
    asm volatile("cp.async.cg.shared.global [%0], [%1], 16;" :: "r"(dst), "l"(src));
}
__device__ __forceinline__ float ex2(float x) {
    float r;
    asm("ex2.approx.f32 %0, %1;" : "=f"(r) : "f"(x));
    return r;
}
__device__ __forceinline__ uint32_t to_tf32(float f) {
    uint32_t u;
    asm("cvt.rna.tf32.f32 %0, %1;" : "=r"(u) : "f"(f));
    return u;
}
__device__ __forceinline__ float trunc13(float x) {
    return __uint_as_float(__float_as_uint(x) & 0xFFFFE000u);
}
__device__ __forceinline__ uint32_t bfpack(float lo, float hi) {
    uint32_t r;
    asm("cvt.rn.bf16x2.f32 %0, %1, %2;" : "=r"(r) : "f"(hi), "f"(lo));
    return r;
}
__device__ __forceinline__ uint32_t bftruncpack(float x0, float x1) {
    return __byte_perm(__float_as_uint(x0), __float_as_uint(x1), 0x7632);
}
__device__ __forceinline__ float bftrunc_res(float x) {
    return x - __uint_as_float(__float_as_uint(x) & 0xFFFF0000u);
}
__device__ __forceinline__ void mma8(float d[4], uint32_t a0, uint32_t a1, uint32_t a2,
                                     uint32_t a3, uint32_t b0, uint32_t b1) {
    asm volatile(
        "mma.sync.aligned.m16n8k8.row.col.f32.tf32.tf32.f32 "
        "{%0,%1,%2,%3}, {%4,%5,%6,%7}, {%8,%9}, {%0,%1,%2,%3};"
        : "+f"(d[0]), "+f"(d[1]), "+f"(d[2]), "+f"(d[3])
        : "r"(a0), "r"(a1), "r"(a2), "r"(a3), "r"(b0), "r"(b1));
}
__device__ __forceinline__ void mma16(float d[4], uint32_t a0, uint32_t a1, uint32_t a2,
                                      uint32_t a3, uint32_t b0, uint32_t b1) {
    asm volatile(
        "mma.sync.aligned.m16n8k16.row.col.f32.bf16.bf16.f32 "
        "{%0,%1,%2,%3}, {%4,%5,%6,%7}, {%8,%9}, {%0,%1,%2,%3};"
        : "+f"(d[0]), "+f"(d[1]), "+f"(d[2]), "+f"(d[3])
        : "r"(a0), "r"(a1), "r"(a2), "r"(a3), "r"(b0), "r"(b1));
}

// ---- flash smem byte offsets (round-12, proven 256 us) ----
#define OFF_QH16 0          /* 8 KB */
#define OFF_QL16 8192       /* 8 KB */
#define OFF_KTH  16384      /* 4 KB */
#define OFF_KTL  20480      /* 4 KB */
#define OFF_P    24576      /* 32 KB */
#define OFF_V    57344      /* 2 x 64 KB */
#define OFF_L    188416
#define OFF_LP   188928
#define FLASH_SMEM 190976

// proven word-index swizzles
__device__ __forceinline__ int pQ16(int r, int w)   { return r * 16 + (w ^ ((r & 7) * 2)); }
__device__ __forceinline__ int pK16(int key, int w) { return key * 16 + (w ^ ((key & 7) * 2)); }
__device__ __forceinline__ int pP(int r, int c)     { return r * 64 + (c ^ ((r & 7) * 4)); }
__device__ __forceinline__ int pV(int k, int n)     { return k * 256 + (n ^ ((k & 3) * 8)); }

// ============================================================================
// Flash attention (round-12/14 verbatim): bf16 3-term QK, tf32 PV.
// ============================================================================
__global__ __launch_bounds__(256, 1)
void flash_mma(const float* __restrict__ Qg,
               const float* __restrict__ KTHg, const float* __restrict__ KTLg,
               const float* __restrict__ Vg, const float* __restrict__ X,
               float* __restrict__ Out) {
    extern __shared__ char smem[];
    uint32_t* sQh = (uint32_t*)(smem + OFF_QH16);
    uint32_t* sQl = (uint32_t*)(smem + OFF_QL16);
    uint32_t* sKh = (uint32_t*)(smem + OFF_KTH);
    uint32_t* sKl = (uint32_t*)(smem + OFF_KTL);
    uint32_t* sPu = (uint32_t*)(smem + OFF_P);
    uint32_t* sVu = (uint32_t*)(smem + OFF_V);
    float*    sL  = (float*)(smem + OFF_L);
    float*    sLp = (float*)(smem + OFF_LP);
    const uint32_t sb = smem_u32(smem);

    const int tid  = threadIdx.x;
    const int lane = tid & 31;
    const int wid  = tid >> 5;
    const int mw   = wid & 1;
    const int nw   = wid >> 1;
    const int g    = lane >> 2;
    const int l4   = lane & 3;
    const int b    = blockIdx.y;
    const int q0   = blockIdx.x * TQ;

    const float* Qb = Qg + ((size_t)b * SEQ + q0) * DDIM;
    const char*  KThb = (const char*)(KTHg + (size_t)b * NT_TILES * 1024);
    const char*  KTlb = (const char*)(KTLg + (size_t)b * NT_TILES * 1024);
    const float* Vb = Vg + (size_t)b * SEQ * CDIM;

    // ---- prologue ----
    if (tid < 128) sL[tid] = 0.0f;
#pragma unroll
    for (int i = 0; i < 4; i++) {
        int idx = tid + i * 256;
        int r = idx >> 3, d4 = idx & 7;
        float4 v = *(const float4*)(Qb + r * DDIM + d4 * 4);
        v.x *= LOG2E; v.y *= LOG2E; v.z *= LOG2E; v.w *= LOG2E;
        uint32_t hi0 = bftruncpack(v.x, v.y);
        uint32_t hi1 = bftruncpack(v.z, v.w);
        uint32_t lo0 = bfpack(bftrunc_res(v.x), bftrunc_res(v.y));
        uint32_t lo1 = bfpack(bftrunc_res(v.z), bftrunc_res(v.w));
        sQh[pQ16(r, 2 * d4)]     = hi0;
        sQh[pQ16(r, 2 * d4 + 1)] = hi1;
        sQl[pQ16(r, 2 * d4)]     = lo0;
        sQl[pQ16(r, 2 * d4 + 1)] = lo1;
    }
    {
        uint32_t off = (uint32_t)tid * 16u;
        cp_async16(sb + OFF_KTH + off, KThb + off);
        cp_async16(sb + OFF_KTL + off, KTlb + off);
    }
#pragma unroll
    for (int i = 0; i < 16; i++) {
        int f = tid + i * 256;
        int key = f >> 6, n4 = f & 63;
        uint32_t dst = sb + OFF_V + (uint32_t)pV(key, n4 * 4) * 4u;
        cp_async16(dst, Vb + (size_t)key * CDIM + n4 * 4);
    }
    asm volatile("cp.async.commit_group;" ::: "memory");
    asm volatile("cp.async.wait_group 0;" ::: "memory");
    __syncthreads();

    float oa[4][8][4];
#pragma unroll
    for (int mt = 0; mt < 4; mt++)
#pragma unroll
        for (int nt = 0; nt < 8; nt++)
#pragma unroll
            for (int c = 0; c < 4; c++) oa[mt][nt][c] = 0.0f;

#pragma unroll 1
    for (int t = 0; t < NT_TILES; t++) {
        const int buf = t & 1;
        const bool have_next = (t + 1 < NT_TILES);

        if (have_next) {
            const float* Vs = Vb + (size_t)(t + 1) * TK * CDIM;
            uint32_t vb0 = sb + OFF_V + (uint32_t)(1 - buf) * 65536u;
#pragma unroll
            for (int i = 0; i < 16; i++) {
                int f = tid + i * 256;
                int key = f >> 6, n4 = f & 63;
                cp_async16(vb0 + (uint32_t)pV(key, n4 * 4) * 4u, Vs + (size_t)key * CDIM + n4 * 4);
            }
            asm volatile("cp.async.commit_group;" ::: "memory");
        }

        // ---- S = QK^T : bf16 3-term ----
        float sa[4][2][4];
#pragma unroll
        for (int mt = 0; mt < 4; mt++)
#pragma unroll
            for (int nt = 0; nt < 2; nt++)
#pragma unroll
                for (int c = 0; c < 4; c++) sa[mt][nt][c] = 0.0f;

#pragma unroll
        for (int kc = 0; kc < 2; kc++) {
            const int w0 = kc * 8;
            uint32_t bh[2][2], bl[2][2];
#pragma unroll
            for (int nt = 0; nt < 2; nt++) {
                int key = nw * 16 + nt * 8 + g;
                bh[nt][0] = sKh[pK16(key, w0 + l4)];
                bh[nt][1] = sKh[pK16(key, w0 + 4 + l4)];
                bl[nt][0] = sKl[pK16(key, w0 + l4)];
                bl[nt][1] = sKl[pK16(key, w0 + 4 + l4)];
            }
#pragma unroll
            for (int mt = 0; mt < 4; mt++) {
                int r0 = mw * 64 + mt * 16 + g;
                uint32_t qh0 = sQh[pQ16(r0, w0 + l4)];
                uint32_t qh1 = sQh[pQ16(r0 + 8, w0 + l4)];
                uint32_t qh2 = sQh[pQ16(r0, w0 + 4 + l4)];
                uint32_t qh3 = sQh[pQ16(r0 + 8, w0 + 4 + l4)];
                uint32_t ql0 = sQl[pQ16(r0, w0 + l4)];
                uint32_t ql1 = sQl[pQ16(r0 + 8, w0 + l4)];
                uint32_t ql2 = sQl[pQ16(r0, w0 + 4 + l4)];
                uint32_t ql3 = sQl[pQ16(r0 + 8, w0 + 4 + l4)];
#pragma unroll
                for (int nt = 0; nt < 2; nt++) {
                    mma16(sa[mt][nt], qh0, qh1, qh2, qh3, bh[nt][0], bh[nt][1]);
                    mma16(sa[mt][nt], qh0, qh1, qh2, qh3, bl[nt][0], bl[nt][1]);
                    mma16(sa[mt][nt], ql0, ql1, ql2, ql3, bh[nt][0], bh[nt][1]);
                }
            }
        }

        // ---- p = 2^s, truncate to tf32, STS.64 pairs, partial sums ----
#pragma unroll
        for (int mt = 0; mt < 4; mt++) {
            int r0 = mw * 64 + mt * 16 + g;
            float s0 = 0.0f, s1 = 0.0f;
#pragma unroll
            for (int nt = 0; nt < 2; nt++) {
                int col = nw * 16 + nt * 8 + l4 * 2;
                uint32_t e0 = __float_as_uint(ex2(sa[mt][nt][0])) & 0xFFFFE000u;
                uint32_t e1 = __float_as_uint(ex2(sa[mt][nt][1])) & 0xFFFFE000u;
                uint32_t e2 = __float_as_uint(ex2(sa[mt][nt][2])) & 0xFFFFE000u;
                uint32_t e3 = __float_as_uint(ex2(sa[mt][nt][3])) & 0xFFFFE000u;
                s0 += __uint_as_float(e0) + __uint_as_float(e1);
                s1 += __uint_as_float(e2) + __uint_as_float(e3);
                uint2 w0p; w0p.x = e0; w0p.y = e1;
                uint2 w1p; w1p.x = e2; w1p.y = e3;
                *(uint2*)(sPu + pP(r0, col)) = w0p;
                *(uint2*)(sPu + pP(r0 + 8, col)) = w1p;
            }
            s0 += __shfl_xor_sync(0xffffffffu, s0, 1);
            s0 += __shfl_xor_sync(0xffffffffu, s0, 2);
            s1 += __shfl_xor_sync(0xffffffffu, s1, 1);
            s1 += __shfl_xor_sync(0xffffffffu, s1, 2);
            if (l4 == 0) {
                sLp[nw * 128 + r0] = s0;
                sLp[nw * 128 + r0 + 8] = s1;
            }
        }
        __syncthreads();   // sync1

        if (have_next) {
            const char* kth_t = KThb + (size_t)(t + 1) * 4096;
            const char* ktl_t = KTlb + (size_t)(t + 1) * 4096;
            uint32_t off = (uint32_t)tid * 16u;
            cp_async16(sb + OFF_KTH + off, kth_t + off);
            cp_async16(sb + OFF_KTL + off, ktl_t + off);
            asm volatile("cp.async.commit_group;" ::: "memory");
        }
        if (tid < 128)
            sL[tid] += (sLp[tid] + sLp[128 + tid]) + (sLp[256 + tid] + sLp[384 + tid]);

        // ---- O += P @ V (tf32) ----
        const uint32_t* sVb = sVu + (size_t)buf * 16384;
#pragma unroll
        for (int ks = 0; ks < 8; ks++) {
            const int k0 = ks * 8;
            uint32_t pa[4][4];
#pragma unroll
            for (int mt = 0; mt < 4; mt++) {
                int r0 = mw * 64 + mt * 16 + g;
                pa[mt][0] = sPu[pP(r0, k0 + l4)];
                pa[mt][1] = sPu[pP(r0 + 8, k0 + l4)];
                pa[mt][2] = sPu[pP(r0, k0 + 4 + l4)];
                pa[mt][3] = sPu[pP(r0 + 8, k0 + 4 + l4)];
            }
#pragma unroll
            for (int nt = 0; nt < 8; nt++) {
                int n = nw * 64 + nt * 8 + g;
                uint32_t b0 = sVb[pV(k0 + l4, n)];
                uint32_t b1 = sVb[pV(k0 + 4 + l4, n)];
#pragma unroll
                for (int mt = 0; mt < 4; mt++)
                    mma8(oa[mt][nt], pa[mt][0], pa[mt][1], pa[mt][2], pa[mt][3], b0, b1);
            }
        }

        asm volatile("cp.async.wait_group 0;" ::: "memory");
        __syncthreads();   // sync2
    }

    // ---- epilogue: O/l + residual ----
#pragma unroll
    for (int mt = 0; mt < 4; mt++) {
        int r0 = mw * 64 + mt * 16 + g;
        float inv0 = 1.0f / sL[r0];
        float inv1 = 1.0f / sL[r0 + 8];
        size_t row0 = (size_t)b * SEQ + q0 + r0;
#pragma unroll
        for (int nt = 0; nt < 8; nt++) {
            int col = nw * 64 + nt * 8 + l4 * 2;
            const float2* x0 = (const float2*)(X + (row0)*CDIM + col);
            const float2* x1 = (const float2*)(X + (row0 + 8) * CDIM + col);
            float2 xv0 = *x0, xv1 = *x1;
            float2 o0, o1;
            o0.x = oa[mt][nt][0] * inv0 + xv0.x;
            o0.y = oa[mt][nt][1] * inv0 + xv0.y;
            o1.x = oa[mt][nt][2] * inv1 + xv1.x;
            o1.y = oa[mt][nt][3] * inv1 + xv1.y;
            *(float2*)(Out + (row0)*CDIM + col) = o0;
            *(float2*)(Out + (row0 + 8) * CDIM + col) = o1;
        }
    }
}

// ============================================================================
// Merged projections:
//   blocks [0,256)   : V projection, single-term tf32 mma (round-12 branch)
//   blocks [256,384) : q/k projection, 3-term compensated tf32 mma
//                      cols [0,32)=q -> Yq fp32; cols [32,64)=k -> bf16 KT layout
// ============================================================================
#define PROJ_SMEM 65536
__device__ __forceinline__ int pA8(int r, int k) { return r * 32 + (k ^ ((r & 7) * 4)); }
__device__ __forceinline__ int pB8(int k, int n) { return k * 128 + (n ^ ((k & 3) * 8)); }
__device__ __forceinline__ int pW64(int k, int n) { return k * 64 + (n ^ ((k & 3) * 8)); }

__global__ __launch_bounds__(256)
void proj_all(const float* __restrict__ Xg,
              const float* __restrict__ Wq, const float* __restrict__ bq,
              const float* __restrict__ Wk, const float* __restrict__ bk,
              const float* __restrict__ Wv, const float* __restrict__ bv,
              float* __restrict__ Yq, float* __restrict__ KTH, float* __restrict__ KTL,
              float* __restrict__ Vout) {
    extern __shared__ char smem[];
    const int tid  = threadIdx.x;
    const int lane = tid & 31;
    const int wid  = tid >> 5;
    const int mw   = wid & 1;
    const int nw   = wid >> 1;
    const int g    = lane >> 2;
    const int l4   = lane & 3;

    if (blockIdx.x < 256) {
        // ---------------- V projection (tf32 mma, single-term) ----------------
        float* sA = (float*)smem;
        float* sB = (float*)(smem + 32768);
        const uint32_t sb = smem_u32(smem);
        const int m0 = (blockIdx.x >> 1) * 128;
        const int n0 = (blockIdx.x & 1) * 128;

        float acc[4][4][4];
#pragma unroll
        for (int mt = 0; mt < 4; mt++)
#pragma unroll
            for (int nt = 0; nt < 4; nt++)
#pragma unroll
                for (int c = 0; c < 4; c++) acc[mt][nt][c] = 0.0f;

        auto load_tiles = [&](int k0, int bufsel) {
            uint32_t abase = sb + (uint32_t)bufsel * 16384u;
            uint32_t bbase = sb + 32768u + (uint32_t)bufsel * 16384u;
#pragma unroll
            for (int i = 0; i < 4; i++) {
                int idx = tid + i * 256;
                int r = idx >> 3, c4 = idx & 7;
                uint32_t dst = abase + (uint32_t)(r * 32 + ((c4 * 4) ^ ((r & 7) * 4))) * 4u;
                cp_async16(dst, Xg + (size_t)(m0 + r) * CDIM + k0 + c4 * 4);
            }
#pragma unroll
            for (int i = 0; i < 4; i++) {
                int idx = tid + i * 256;
                int k = idx >> 5, n4 = idx & 31;
                uint32_t dst = bbase + (uint32_t)(k * 128 + ((n4 * 4) ^ ((k & 3) * 8))) * 4u;
                cp_async16(dst, Wv + (size_t)(k0 + k) * CDIM + n0 + n4 * 4);
            }
            asm volatile("cp.async.commit_group;" ::: "memory");
        };

        load_tiles(0, 0);

#pragma unroll 1
        for (int t = 0; t < 8; t++) {
            const int buf = t & 1;
            const bool have_next = (t + 1 < 8);
            if (have_next) load_tiles((t + 1) * 32, 1 - buf);
            if (have_next) asm volatile("cp.async.wait_group 1;" ::: "memory");
            else           asm volatile("cp.async.wait_group 0;" ::: "memory");
            __syncthreads();

            const float* A = sA + (size_t)buf * 4096;
            const float* B = sB + (size_t)buf * 4096;
#pragma unroll
            for (int ks = 0; ks < 4; ks++) {
                const int k8 = ks * 8;
                uint32_t bfr[4][2];
#pragma unroll
                for (int nt = 0; nt < 4; nt++) {
                    int n = nw * 32 + nt * 8 + g;
                    bfr[nt][0] = __float_as_uint(B[pB8(k8 + l4, n)]);
                    bfr[nt][1] = __float_as_uint(B[pB8(k8 + 4 + l4, n)]);
                }
#pragma unroll
                for (int mt = 0; mt < 4; mt++) {
                    int r0 = mw * 64 + mt * 16 + g;
                    uint32_t a0 = __float_as_uint(A[pA8(r0, k8 + l4)]);
                    uint32_t a1 = __float_as_uint(A[pA8(r0 + 8, k8 + l4)]);
                    uint32_t a2 = __float_as_uint(A[pA8(r0, k8 + 4 + l4)]);
                    uint32_t a3 = __float_as_uint(A[pA8(r0 + 8, k8 + 4 + l4)]);
#pragma unroll
                    for (int nt = 0; nt < 4; nt++)
                        mma8(acc[mt][nt], a0, a1, a2, a3, bfr[nt][0], bfr[nt][1]);
                }
            }
            __syncthreads();
        }

#pragma unroll
        for (int mt = 0; mt < 4; mt++) {
            int r0 = m0 + mw * 64 + mt * 16 + g;
#pragma unroll
            for (int nt = 0; nt < 4; nt++) {
                int col = n0 + nw * 32 + nt * 8 + l4 * 2;
                float2 bb = *(const float2*)(bv + col);
                float2 o0, o1;
                o0.x = acc[mt][nt][0] + bb.x;
                o0.y = acc[mt][nt][1] + bb.y;
                o1.x = acc[mt][nt][2] + bb.x;
                o1.y = acc[mt][nt][3] + bb.y;
                *(float2*)(Vout + (size_t)r0 * CDIM + col) = o0;
                *(float2*)(Vout + (size_t)(r0 + 8) * CDIM + col) = o1;
            }
        }
    } else {
        // ------------- q/k projection: tf32 3-term compensated mma -------------
        float* sXh = (float*)smem;               // [128][32] 16 KB
        float* sXl = (float*)(smem + 16384);     // 16 KB
        float* sWh = (float*)(smem + 32768);     // [32][64]  8 KB
        float* sWl = (float*)(smem + 40960);     // 8 KB
        const int m0 = (blockIdx.x - 256) * 128;

        float acc[4][2][4];
#pragma unroll
        for (int mt = 0; mt < 4; mt++)
#pragma unroll
            for (int nt = 0; nt < 2; nt++)
#pragma unroll
                for (int c = 0; c < 4; c++) acc[mt][nt][c] = 0.0f;

#pragma unroll 1
        for (int kt = 0; kt < 8; kt++) {
            const int k0 = kt * 32;
            // X tile [128][32], hi/lo split
#pragma unroll
            for (int i = 0; i < 4; i++) {
                int idx = tid + i * 256;
                int r = idx >> 3, c4 = idx & 7;
                float4 v = *(const float4*)(Xg + (size_t)(m0 + r) * CDIM + k0 + c4 * 4);
                float4 hi, lo;
                hi.x = trunc13(v.x); lo.x = __uint_as_float(to_tf32(v.x - hi.x));
                hi.y = trunc13(v.y); lo.y = __uint_as_float(to_tf32(v.y - hi.y));
                hi.z = trunc13(v.z); lo.z = __uint_as_float(to_tf32(v.z - hi.z));
                hi.w = trunc13(v.w); lo.w = __uint_as_float(to_tf32(v.w - hi.w));
                int base = r * 32 + ((c4 * 4) ^ ((r & 7) * 4));
                *(float4*)(sXh + base) = hi;
                *(float4*)(sXl + base) = lo;
            }
            // W tile [32][64] = [Wq | Wk], hi/lo split
#pragma unroll
            for (int i = 0; i < 2; i++) {
                int idx = tid + i * 256;
                int kk = idx >> 4, c4 = idx & 15;
                const float* src = (c4 < 8)
                    ? (Wq + (size_t)(k0 + kk) * DDIM + c4 * 4)
                    : (Wk + (size_t)(k0 + kk) * DDIM + (c4 - 8) * 4);
                float4 v = *(const float4*)src;
                float4 hi, lo;
                hi.x = trunc13(v.x); lo.x = __uint_as_float(to_tf32(v.x - hi.x));
                hi.y = trunc13(v.y); lo.y = __uint_as_float(to_tf32(v.y - hi.y));
                hi.z = trunc13(v.z); lo.z = __uint_as_float(to_tf32(v.z - hi.z));
                hi.w = trunc13(v.w); lo.w = __uint_as_float(to_tf32(v.w - hi.w));
                int base = kk * 64 + ((c4 * 4) ^ ((kk & 3) * 8));
                *(float4*)(sWh + base) = hi;
                *(float4*)(sWl + base) = lo;
            }
            __syncthreads();

#pragma unroll
            for (int ks = 0; ks < 4; ks++) {
                const int k8 = ks * 8;
                uint32_t bh[2][2], bl[2][2];
#pragma unroll
                for (int nt = 0; nt < 2; nt++) {
                    int n = nw * 16 + nt * 8 + g;
                    bh[nt][0] = __float_as_uint(sWh[pW64(k8 + l4, n)]);
                    bh[nt][1] = __float_as_uint(sWh[pW64(k8 + 4 + l4, n)]);
                    bl[nt][0] = __float_as_uint(sWl[pW64(k8 + l4, n)]);
                    bl[nt][1] = __float_as_uint(sWl[pW64(k8 + 4 + l4, n)]);
                }
#pragma unroll
                for (int mt = 0; mt < 4; mt++) {
                    int r0 = mw * 64 + mt * 16 + g;
                    uint32_t ah0 = __float_as_uint(sXh[pA8(r0, k8 + l4)]);
                    uint32_t ah1 = __float_as_uint(sXh[pA8(r0 + 8, k8 + l4)]);
                    uint32_t ah2 = __float_as_uint(sXh[pA8(r0, k8 + 4 + l4)]);
                    uint32_t ah3 = __float_as_uint(sXh[pA8(r0 + 8, k8 + 4 + l4)]);
                    uint32_t al0 = __float_as_uint(sXl[pA8(r0, k8 + l4)]);
                    uint32_t al1 = __float_as_uint(sXl[pA8(r0 + 8, k8 + l4)]);
                    uint32_t al2 = __float_as_uint(sXl[pA8(r0, k8 + 4 + l4)]);
                    uint32_t al3 = __float_as_uint(sXl[pA8(r0 + 8, k8 + 4 + l4)]);
#pragma unroll
                    for (int nt = 0; nt < 2; nt++) {
                        mma8(acc[mt][nt], ah0, ah1, ah2, ah3, bh[nt][0], bh[nt][1]);
                        mma8(acc[mt][nt], ah0, ah1, ah2, ah3, bl[nt][0], bl[nt][1]);
                        mma8(acc[mt][nt], al0, al1, al2, al3, bh[nt][0], bh[nt][1]);
                    }
                }
            }
            __syncthreads();
        }

        // epilogue: nw<2 -> q (cols 0..31, fp32); nw>=2 -> k (cols 32..63, bf16 KT)
        if (nw < 2) {
#pragma unroll
            for (int mt = 0; mt < 4; mt++) {
                int m = m0 + mw * 64 + mt * 16 + g;
#pragma unroll
                for (int nt = 0; nt < 2; nt++) {
                    int col = nw * 16 + nt * 8 + l4 * 2;
                    float2 bb = *(const float2*)(bq + col);
                    float2 o0, o1;
                    o0.x = acc[mt][nt][0] + bb.x;
                    o0.y = acc[mt][nt][1] + bb.y;
                    o1.x = acc[mt][nt][2] + bb.x;
                    o1.y = acc[mt][nt][3] + bb.y;
                    *(float2*)(Yq + (size_t)m * DDIM + col) = o0;
                    *(float2*)(Yq + (size_t)(m + 8) * DDIM + col) = o1;
                }
            }
        } else {
#pragma unroll
            for (int mt = 0; mt < 4; mt++) {
                int m = m0 + mw * 64 + mt * 16 + g;
#pragma unroll
                for (int nt = 0; nt < 2; nt++) {
                    int d = (nw - 2) * 16 + nt * 8 + l4 * 2;
                    int w = (nw - 2) * 8 + nt * 4 + l4;
                    float2 bb = *(const float2*)(bk + d);
                    // row m
                    {
                        float v0 = acc[mt][nt][0] + bb.x;
                        float v1 = acc[mt][nt][1] + bb.y;
                        size_t idx = (size_t)(m >> 6) * 1024 + pK16(m & 63, w);
                        ((uint32_t*)KTH)[idx] = bftruncpack(v0, v1);
                        ((uint32_t*)KTL)[idx] = bfpack(bftrunc_res(v0), bftrunc_res(v1));
                    }
                    // row m+8
                    {
                        float v0 = acc[mt][nt][2] + bb.x;
                        float v1 = acc[mt][nt][3] + bb.y;
                        int m8 = m + 8;
                        size_t idx = (size_t)(m8 >> 6) * 1024 + pK16(m8 & 63, w);
                        ((uint32_t*)KTH)[idx] = bftruncpack(v0, v1);
                        ((uint32_t*)KTL)[idx] = bfpack(bftrunc_res(v0), bftrunc_res(v1));
                    }
                }
            }
        }
    }
}

// ============================================================================
extern "C" void kernel_launch(void* const* d_in, const int* in_sizes, int n_in,
                              void* d_out, int out_size) {
    const float* x  = (const float*)d_in[0];
    const float* wq = (const float*)d_in[1];
    const float* bq = (const float*)d_in[2];
    const float* wk = (const float*)d_in[3];
    const float* bk = (const float*)d_in[4];
    const float* wv = (const float*)d_in[5];
    const float* bv = (const float*)d_in[6];
    float* out = (float*)d_out;

    float *qp, *kthp, *ktlp, *vp;
    cudaGetSymbolAddress((void**)&qp, g_q);
    cudaGetSymbolAddress((void**)&kthp, g_kth);
    cudaGetSymbolAddress((void**)&ktlp, g_ktl);
    cudaGetSymbolAddress((void**)&vp, g_v);

    {
        cudaFuncSetAttribute(proj_all, cudaFuncAttributeMaxDynamicSharedMemorySize, PROJ_SMEM);
        proj_all<<<384, 256, PROJ_SMEM>>>(x, wq, bq, wk, bk, wv, bv, qp, kthp, ktlp, vp);
    }
    {
        cudaFuncSetAttribute(flash_mma, cudaFuncAttributeMaxDynamicSharedMemorySize, FLASH_SMEM);
        dim3 g(SEQ / TQ, BATCH);
        flash_mma<<<g, 256, FLASH_SMEM>>>(qp, kthp, ktlp, vp, x, out);
    }
}

// round 16
// speedup vs baseline: 1.1770x; 1.0325x over previous
#include <cuda_runtime.h>
#include <cstdint>

#define BATCH 4
#define SEQ   4096
#define CDIM  256
#define DDIM  32
#define TQ    64
#define TK    64
#define NT_TILES (SEQ / TK)
#define LOG2E 1.4426950408889634f

// ---- scratch ----
__device__ float g_q[BATCH * SEQ * DDIM];
__device__ float g_kth[BATCH * NT_TILES * 1024];   // K-hi bf16x2 words, KT tile layout
__device__ float g_ktl[BATCH * NT_TILES * 1024];   // K-lo bf16x2 words
__device__ float g_v[BATCH * SEQ * CDIM];

// ---- helpers ----
__device__ __forceinline__ uint32_t smem_u32(const void* p) {
    uint32_t a;
    asm("{ .reg .u64 t; cvta.to.shared.u64 t, %1; cvt.u32.u64 %0, t; }" : "=r"(a) : "l"(p));
    return a;
}
__device__ __forceinline__ void cp_async16(uint32_t dst, const void* src) {
    asm volatile("cp.async.cg.shared.global [%0], [%1], 16;" :: "r"(dst), "l"(src));
}
__device__ __forceinline__ float ex2(float x) {
    float r;
    asm("ex2.approx.f32 %0, %1;" : "=f"(r) : "f"(x));
    return r;
}
__device__ __forceinline__ uint32_t to_tf32(float f) {
    uint32_t u;
    asm("cvt.rna.tf32.f32 %0, %1;" : "=r"(u) : "f"(f));
    return u;
}
__device__ __forceinline__ float trunc13(float x) {
    return __uint_as_float(__float_as_uint(x) & 0xFFFFE000u);
}
__device__ __forceinline__ uint32_t bfpack(float lo, float hi) {
    uint32_t r;
    asm("cvt.rn.bf16x2.f32 %0, %1, %2;" : "=r"(r) : "f"(hi), "f"(lo));
    return r;
}
__device__ __forceinline__ uint32_t bftruncpack(float x0, float x1) {
    return __byte_perm(__float_as_uint(x0), __float_as_uint(x1), 0x7632);
}
__device__ __forceinline__ float bftrunc_res(float x) {
    return x - __uint_as_float(__float_as_uint(x) & 0xFFFF0000u);
}
__device__ __forceinline__ void mma8(float d[4], uint32_t a0, uint32_t a1, uint32_t a2,
                                     uint32_t a3, uint32_t b0, uint32_t b1) {
    asm volatile(
        "mma.sync.aligned.m16n8k8.row.col.f32.tf32.tf32.f32 "
        "{%0,%1,%2,%3}, {%4,%5,%6,%7}, {%8,%9}, {%0,%1,%2,%3};"
        : "+f"(d[0]), "+f"(d[1]), "+f"(d[2]), "+f"(d[3])
        : "r"(a0), "r"(a1), "r"(a2), "r"(a3), "r"(b0), "r"(b1));
}
__device__ __forceinline__ void mma16(float d[4], uint32_t a0, uint32_t a1, uint32_t a2,
                                      uint32_t a3, uint32_t b0, uint32_t b1) {
    asm volatile(
        "mma.sync.aligned.m16n8k16.row.col.f32.bf16.bf16.f32 "
        "{%0,%1,%2,%3}, {%4,%5,%6,%7}, {%8,%9}, {%0,%1,%2,%3};"
        : "+f"(d[0]), "+f"(d[1]), "+f"(d[2]), "+f"(d[3])
        : "r"(a0), "r"(a1), "r"(a2), "r"(a3), "r"(b0), "r"(b1));
}

// ---- flash smem byte offsets (64-row CTA, single-buffered V) ----
#define OFF_QH16 0          /* 4 KB : 64 rows x 16 words */
#define OFF_QL16 4096       /* 4 KB */
#define OFF_KTH  8192       /* 4 KB */
#define OFF_KTL  12288      /* 4 KB */
#define OFF_P    16384      /* 16 KB : 64 x 64 */
#define OFF_V    32768      /* 64 KB (single buffer) */
#define OFF_L    98304      /* 256 B */
#define OFF_LP   98560      /* 1 KB */
#define FLASH_SMEM 99584

// proven word-index swizzles
__device__ __forceinline__ int pQ16(int r, int w)   { return r * 16 + (w ^ ((r & 7) * 2)); }
__device__ __forceinline__ int pK16(int key, int w) { return key * 16 + (w ^ ((key & 7) * 2)); }
__device__ __forceinline__ int pP(int r, int c)     { return r * 64 + (c ^ ((r & 7) * 4)); }
__device__ __forceinline__ int pV(int k, int n)     { return k * 256 + (n ^ ((k & 3) * 8)); }

// ============================================================================
// Flash attention: 64 q-rows per CTA, 128 threads = 4 warps (nw = wid),
// 2 CTAs/SM for cross-CTA phase overlap. Inner math identical to round-12.
// ============================================================================
__global__ __launch_bounds__(128, 2)
void flash_mma(const float* __restrict__ Qg,
               const float* __restrict__ KTHg, const float* __restrict__ KTLg,
               const float* __restrict__ Vg, const float* __restrict__ X,
               float* __restrict__ Out) {
    extern __shared__ char smem[];
    uint32_t* sQh = (uint32_t*)(smem + OFF_QH16);
    uint32_t* sQl = (uint32_t*)(smem + OFF_QL16);
    uint32_t* sKh = (uint32_t*)(smem + OFF_KTH);
    uint32_t* sKl = (uint32_t*)(smem + OFF_KTL);
    uint32_t* sPu = (uint32_t*)(smem + OFF_P);
    uint32_t* sVu = (uint32_t*)(smem + OFF_V);
    float*    sL  = (float*)(smem + OFF_L);
    float*    sLp = (float*)(smem + OFF_LP);
    const uint32_t sb = smem_u32(smem);

    const int tid  = threadIdx.x;
    const int lane = tid & 31;
    const int nw   = tid >> 5;         // warp 0..3
    const int g    = lane >> 2;
    const int l4   = lane & 3;
    const int b    = blockIdx.y;
    const int q0   = blockIdx.x * TQ;

    const float* Qb = Qg + ((size_t)b * SEQ + q0) * DDIM;
    const char*  KThb = (const char*)(KTHg + (size_t)b * NT_TILES * 1024);
    const char*  KTlb = (const char*)(KTLg + (size_t)b * NT_TILES * 1024);
    const float* Vb = Vg + (size_t)b * SEQ * CDIM;

    // ---- prologue ----
    if (tid < 64) sL[tid] = 0.0f;
#pragma unroll
    for (int i = 0; i < 4; i++) {
        int idx = tid + i * 128;
        int r = idx >> 3, d4 = idx & 7;
        float4 v = *(const float4*)(Qb + r * DDIM + d4 * 4);
        v.x *= LOG2E; v.y *= LOG2E; v.z *= LOG2E; v.w *= LOG2E;
        uint32_t hi0 = bftruncpack(v.x, v.y);
        uint32_t hi1 = bftruncpack(v.z, v.w);
        uint32_t lo0 = bfpack(bftrunc_res(v.x), bftrunc_res(v.y));
        uint32_t lo1 = bfpack(bftrunc_res(v.z), bftrunc_res(v.w));
        sQh[pQ16(r, 2 * d4)]     = hi0;
        sQh[pQ16(r, 2 * d4 + 1)] = hi1;
        sQl[pQ16(r, 2 * d4)]     = lo0;
        sQl[pQ16(r, 2 * d4 + 1)] = lo1;
    }
#pragma unroll
    for (int i = 0; i < 2; i++) {
        uint32_t off = (uint32_t)(tid + i * 128) * 16u;
        cp_async16(sb + OFF_KTH + off, KThb + off);
        cp_async16(sb + OFF_KTL + off, KTlb + off);
    }
#pragma unroll
    for (int i = 0; i < 32; i++) {
        int f = tid + i * 128;
        int key = f >> 6, n4 = f & 63;
        uint32_t dst = sb + OFF_V + (uint32_t)pV(key, n4 * 4) * 4u;
        cp_async16(dst, Vb + (size_t)key * CDIM + n4 * 4);
    }
    asm volatile("cp.async.commit_group;" ::: "memory");
    asm volatile("cp.async.wait_group 0;" ::: "memory");
    __syncthreads();

    float oa[4][8][4];
#pragma unroll
    for (int mt = 0; mt < 4; mt++)
#pragma unroll
        for (int nt = 0; nt < 8; nt++)
#pragma unroll
            for (int c = 0; c < 4; c++) oa[mt][nt][c] = 0.0f;

#pragma unroll 1
    for (int t = 0; t < NT_TILES; t++) {
        const bool have_next = (t + 1 < NT_TILES);

        // ---- S = QK^T : bf16 3-term (KT(t) in smem) ----
        float sa[4][2][4];
#pragma unroll
        for (int mt = 0; mt < 4; mt++)
#pragma unroll
            for (int nt = 0; nt < 2; nt++)
#pragma unroll
                for (int c = 0; c < 4; c++) sa[mt][nt][c] = 0.0f;

#pragma unroll
        for (int kc = 0; kc < 2; kc++) {
            const int w0 = kc * 8;
            uint32_t bh[2][2], bl[2][2];
#pragma unroll
            for (int nt = 0; nt < 2; nt++) {
                int key = nw * 16 + nt * 8 + g;
                bh[nt][0] = sKh[pK16(key, w0 + l4)];
                bh[nt][1] = sKh[pK16(key, w0 + 4 + l4)];
                bl[nt][0] = sKl[pK16(key, w0 + l4)];
                bl[nt][1] = sKl[pK16(key, w0 + 4 + l4)];
            }
#pragma unroll
            for (int mt = 0; mt < 4; mt++) {
                int r0 = mt * 16 + g;
                uint32_t qh0 = sQh[pQ16(r0, w0 + l4)];
                uint32_t qh1 = sQh[pQ16(r0 + 8, w0 + l4)];
                uint32_t qh2 = sQh[pQ16(r0, w0 + 4 + l4)];
                uint32_t qh3 = sQh[pQ16(r0 + 8, w0 + 4 + l4)];
                uint32_t ql0 = sQl[pQ16(r0, w0 + l4)];
                uint32_t ql1 = sQl[pQ16(r0 + 8, w0 + l4)];
                uint32_t ql2 = sQl[pQ16(r0, w0 + 4 + l4)];
                uint32_t ql3 = sQl[pQ16(r0 + 8, w0 + 4 + l4)];
#pragma unroll
                for (int nt = 0; nt < 2; nt++) {
                    mma16(sa[mt][nt], qh0, qh1, qh2, qh3, bh[nt][0], bh[nt][1]);
                    mma16(sa[mt][nt], qh0, qh1, qh2, qh3, bl[nt][0], bl[nt][1]);
                    mma16(sa[mt][nt], ql0, ql1, ql2, ql3, bh[nt][0], bh[nt][1]);
                }
            }
        }

        // ---- p = 2^s, truncate to tf32, STS.64 pairs, partial sums ----
#pragma unroll
        for (int mt = 0; mt < 4; mt++) {
            int r0 = mt * 16 + g;
            float s0 = 0.0f, s1 = 0.0f;
#pragma unroll
            for (int nt = 0; nt < 2; nt++) {
                int col = nw * 16 + nt * 8 + l4 * 2;
                uint32_t e0 = __float_as_uint(ex2(sa[mt][nt][0])) & 0xFFFFE000u;
                uint32_t e1 = __float_as_uint(ex2(sa[mt][nt][1])) & 0xFFFFE000u;
                uint32_t e2 = __float_as_uint(ex2(sa[mt][nt][2])) & 0xFFFFE000u;
                uint32_t e3 = __float_as_uint(ex2(sa[mt][nt][3])) & 0xFFFFE000u;
                s0 += __uint_as_float(e0) + __uint_as_float(e1);
                s1 += __uint_as_float(e2) + __uint_as_float(e3);
                uint2 w0p; w0p.x = e0; w0p.y = e1;
                uint2 w1p; w1p.x = e2; w1p.y = e3;
                *(uint2*)(sPu + pP(r0, col)) = w0p;
                *(uint2*)(sPu + pP(r0 + 8, col)) = w1p;
            }
            s0 += __shfl_xor_sync(0xffffffffu, s0, 1);
            s0 += __shfl_xor_sync(0xffffffffu, s0, 2);
            s1 += __shfl_xor_sync(0xffffffffu, s1, 1);
            s1 += __shfl_xor_sync(0xffffffffu, s1, 2);
            if (l4 == 0) {
                sLp[nw * 64 + r0] = s0;
                sLp[nw * 64 + r0 + 8] = s1;
            }
        }
        // V(t) copies done (this thread), then publish P + V to all threads
        asm volatile("cp.async.wait_group 0;" ::: "memory");
        __syncthreads();   // sync1: sP/sLp/V(t) visible; KT free (QK done)

        // ---- issue KT(t+1) into the (now free) KT buffer ----
        if (have_next) {
            const char* kth_t = KThb + (size_t)(t + 1) * 4096;
            const char* ktl_t = KTlb + (size_t)(t + 1) * 4096;
#pragma unroll
            for (int i = 0; i < 2; i++) {
                uint32_t off = (uint32_t)(tid + i * 128) * 16u;
                cp_async16(sb + OFF_KTH + off, kth_t + off);
                cp_async16(sb + OFF_KTL + off, ktl_t + off);
            }
            asm volatile("cp.async.commit_group;" ::: "memory");
        }
        if (tid < 64)
            sL[tid] += (sLp[tid] + sLp[64 + tid]) + (sLp[128 + tid] + sLp[192 + tid]);

        // ---- O += P @ V (tf32) ----
#pragma unroll
        for (int ks = 0; ks < 8; ks++) {
            const int k0 = ks * 8;
            uint32_t pa[4][4];
#pragma unroll
            for (int mt = 0; mt < 4; mt++) {
                int r0 = mt * 16 + g;
                pa[mt][0] = sPu[pP(r0, k0 + l4)];
                pa[mt][1] = sPu[pP(r0 + 8, k0 + l4)];
                pa[mt][2] = sPu[pP(r0, k0 + 4 + l4)];
                pa[mt][3] = sPu[pP(r0 + 8, k0 + 4 + l4)];
            }
#pragma unroll
            for (int nt = 0; nt < 8; nt++) {
                int n = nw * 64 + nt * 8 + g;
                uint32_t b0 = sVu[pV(k0 + l4, n)];
                uint32_t b1 = sVu[pV(k0 + 4 + l4, n)];
#pragma unroll
                for (int mt = 0; mt < 4; mt++)
                    mma8(oa[mt][nt], pa[mt][0], pa[mt][1], pa[mt][2], pa[mt][3], b0, b1);
            }
        }

        // KT(t+1) done (this thread), publish; free sP and sV
        asm volatile("cp.async.wait_group 0;" ::: "memory");
        __syncthreads();   // sync2

        // ---- issue V(t+1) into the (now free) single V buffer ----
        if (have_next) {
            const float* Vs = Vb + (size_t)(t + 1) * TK * CDIM;
#pragma unroll
            for (int i = 0; i < 32; i++) {
                int f = tid + i * 128;
                int key = f >> 6, n4 = f & 63;
                cp_async16(sb + OFF_V + (uint32_t)pV(key, n4 * 4) * 4u,
                           Vs + (size_t)key * CDIM + n4 * 4);
            }
            asm volatile("cp.async.commit_group;" ::: "memory");
        }
    }

    // ---- epilogue: O/l + residual ----
#pragma unroll
    for (int mt = 0; mt < 4; mt++) {
        int r0 = mt * 16 + g;
        float inv0 = 1.0f / sL[r0];
        float inv1 = 1.0f / sL[r0 + 8];
        size_t row0 = (size_t)b * SEQ + q0 + r0;
#pragma unroll
        for (int nt = 0; nt < 8; nt++) {
            int col = nw * 64 + nt * 8 + l4 * 2;
            const float2* x0 = (const float2*)(X + (row0)*CDIM + col);
            const float2* x1 = (const float2*)(X + (row0 + 8) * CDIM + col);
            float2 xv0 = *x0, xv1 = *x1;
            float2 o0, o1;
            o0.x = oa[mt][nt][0] * inv0 + xv0.x;
            o0.y = oa[mt][nt][1] * inv0 + xv0.y;
            o1.x = oa[mt][nt][2] * inv1 + xv1.x;
            o1.y = oa[mt][nt][3] * inv1 + xv1.y;
            *(float2*)(Out + (row0)*CDIM + col) = o0;
            *(float2*)(Out + (row0 + 8) * CDIM + col) = o1;
        }
    }
}

// ============================================================================
// Merged projections (round-15, passing):
//   blocks [0,256)   : V projection, single-term tf32 mma
//   blocks [256,384) : q/k projection, 3-term compensated tf32 mma
// ============================================================================
#define PROJ_SMEM 65536
__device__ __forceinline__ int pA8(int r, int k) { return r * 32 + (k ^ ((r & 7) * 4)); }
__device__ __forceinline__ int pB8(int k, int n) { return k * 128 + (n ^ ((k & 3) * 8)); }
__device__ __forceinline__ int pW64(int k, int n) { return k * 64 + (n ^ ((k & 3) * 8)); }

__global__ __launch_bounds__(256)
void proj_all(const float* __restrict__ Xg,
              const float* __restrict__ Wq, const float* __restrict__ bq,
              const float* __restrict__ Wk, const float* __restrict__ bk,
              const float* __restrict__ Wv, const float* __restrict__ bv,
              float* __restrict__ Yq, float* __restrict__ KTH, float* __restrict__ KTL,
              float* __restrict__ Vout) {
    extern __shared__ char smem[];
    const int tid  = threadIdx.x;
    const int lane = tid & 31;
    const int wid  = tid >> 5;
    const int mw   = wid & 1;
    const int nw   = wid >> 1;
    const int g    = lane >> 2;
    const int l4   = lane & 3;

    if (blockIdx.x < 256) {
        float* sA = (float*)smem;
        float* sB = (float*)(smem + 32768);
        const uint32_t sb = smem_u32(smem);
        const int m0 = (blockIdx.x >> 1) * 128;
        const int n0 = (blockIdx.x & 1) * 128;

        float acc[4][4][4];
#pragma unroll
        for (int mt = 0; mt < 4; mt++)
#pragma unroll
            for (int nt = 0; nt < 4; nt++)
#pragma unroll
                for (int c = 0; c < 4; c++) acc[mt][nt][c] = 0.0f;

        auto load_tiles = [&](int k0, int bufsel) {
            uint32_t abase = sb + (uint32_t)bufsel * 16384u;
            uint32_t bbase = sb + 32768u + (uint32_t)bufsel * 16384u;
#pragma unroll
            for (int i = 0; i < 4; i++) {
                int idx = tid + i * 256;
                int r = idx >> 3, c4 = idx & 7;
                uint32_t dst = abase + (uint32_t)(r * 32 + ((c4 * 4) ^ ((r & 7) * 4))) * 4u;
                cp_async16(dst, Xg + (size_t)(m0 + r) * CDIM + k0 + c4 * 4);
            }
#pragma unroll
            for (int i = 0; i < 4; i++) {
                int idx = tid + i * 256;
                int k = idx >> 5, n4 = idx & 31;
                uint32_t dst = bbase + (uint32_t)(k * 128 + ((n4 * 4) ^ ((k & 3) * 8))) * 4u;
                cp_async16(dst, Wv + (size_t)(k0 + k) * CDIM + n0 + n4 * 4);
            }
            asm volatile("cp.async.commit_group;" ::: "memory");
        };

        load_tiles(0, 0);

#pragma unroll 1
        for (int t = 0; t < 8; t++) {
            const int buf = t & 1;
            const bool have_next = (t + 1 < 8);
            if (have_next) load_tiles((t + 1) * 32, 1 - buf);
            if (have_next) asm volatile("cp.async.wait_group 1;" ::: "memory");
            else           asm volatile("cp.async.wait_group 0;" ::: "memory");
            __syncthreads();

            const float* A = sA + (size_t)buf * 4096;
            const float* B = sB + (size_t)buf * 4096;
#pragma unroll
            for (int ks = 0; ks < 4; ks++) {
                const int k8 = ks * 8;
                uint32_t bfr[4][2];
#pragma unroll
                for (int nt = 0; nt < 4; nt++) {
                    int n = nw * 32 + nt * 8 + g;
                    bfr[nt][0] = __float_as_uint(B[pB8(k8 + l4, n)]);
                    bfr[nt][1] = __float_as_uint(B[pB8(k8 + 4 + l4, n)]);
                }
#pragma unroll
                for (int mt = 0; mt < 4; mt++) {
                    int r0 = mw * 64 + mt * 16 + g;
                    uint32_t a0 = __float_as_uint(A[pA8(r0, k8 + l4)]);
                    uint32_t a1 = __float_as_uint(A[pA8(r0 + 8, k8 + l4)]);
                    uint32_t a2 = __float_as_uint(A[pA8(r0, k8 + 4 + l4)]);
                    uint32_t a3 = __float_as_uint(A[pA8(r0 + 8, k8 + 4 + l4)]);
#pragma unroll
                    for (int nt = 0; nt < 4; nt++)
                        mma8(acc[mt][nt], a0, a1, a2, a3, bfr[nt][0], bfr[nt][1]);
                }
            }
            __syncthreads();
        }

#pragma unroll
        for (int mt = 0; mt < 4; mt++) {
            int r0 = m0 + mw * 64 + mt * 16 + g;
#pragma unroll
            for (int nt = 0; nt < 4; nt++) {
                int col = n0 + nw * 32 + nt * 8 + l4 * 2;
                float2 bb = *(const float2*)(bv + col);
                float2 o0, o1;
                o0.x = acc[mt][nt][0] + bb.x;
                o0.y = acc[mt][nt][1] + bb.y;
                o1.x = acc[mt][nt][2] + bb.x;
                o1.y = acc[mt][nt][3] + bb.y;
                *(float2*)(Vout + (size_t)r0 * CDIM + col) = o0;
                *(float2*)(Vout + (size_t)(r0 + 8) * CDIM + col) = o1;
            }
        }
    } else {
        float* sXh = (float*)smem;
        float* sXl = (float*)(smem + 16384);
        float* sWh = (float*)(smem + 32768);
        float* sWl = (float*)(smem + 40960);
        const int m0 = (blockIdx.x - 256) * 128;

        float acc[4][2][4];
#pragma unroll
        for (int mt = 0; mt < 4; mt++)
#pragma unroll
            for (int nt = 0; nt < 2; nt++)
#pragma unroll
                for (int c = 0; c < 4; c++) acc[mt][nt][c] = 0.0f;

#pragma unroll 1
        for (int kt = 0; kt < 8; kt++) {
            const int k0 = kt * 32;
#pragma unroll
            for (int i = 0; i < 4; i++) {
                int idx = tid + i * 256;
                int r = idx >> 3, c4 = idx & 7;
                float4 v = *(const float4*)(Xg + (size_t)(m0 + r) * CDIM + k0 + c4 * 4);
                float4 hi, lo;
                hi.x = trunc13(v.x); lo.x = __uint_as_float(to_tf32(v.x - hi.x));
                hi.y = trunc13(v.y); lo.y = __uint_as_float(to_tf32(v.y - hi.y));
                hi.z = trunc13(v.z); lo.z = __uint_as_float(to_tf32(v.z - hi.z));
                hi.w = trunc13(v.w); lo.w = __uint_as_float(to_tf32(v.w - hi.w));
                int base = r * 32 + ((c4 * 4) ^ ((r & 7) * 4));
                *(float4*)(sXh + base) = hi;
                *(float4*)(sXl + base) = lo;
            }
#pragma unroll
            for (int i = 0; i < 2; i++) {
                int idx = tid + i * 256;
                int kk = idx >> 4, c4 = idx & 15;
                const float* src = (c4 < 8)
                    ? (Wq + (size_t)(k0 + kk) * DDIM + c4 * 4)
                    : (Wk + (size_t)(k0 + kk) * DDIM + (c4 - 8) * 4);
                float4 v = *(const float4*)src;
                float4 hi, lo;
                hi.x = trunc13(v.x); lo.x = __uint_as_float(to_tf32(v.x - hi.x));
                hi.y = trunc13(v.y); lo.y = __uint_as_float(to_tf32(v.y - hi.y));
                hi.z = trunc13(v.z); lo.z = __uint_as_float(to_tf32(v.z - hi.z));
                hi.w = trunc13(v.w); lo.w = __uint_as_float(to_tf32(v.w - hi.w));
                int base = kk * 64 + ((c4 * 4) ^ ((kk & 3) * 8));
                *(float4*)(sWh + base) = hi;
                *(float4*)(sWl + base) = lo;
            }
            __syncthreads();

#pragma unroll
            for (int ks = 0; ks < 4; ks++) {
                const int k8 = ks * 8;
                uint32_t bh[2][2], bl[2][2];
#pragma unroll
                for (int nt = 0; nt < 2; nt++) {
                    int n = nw * 16 + nt * 8 + g;
                    bh[nt][0] = __float_as_uint(sWh[pW64(k8 + l4, n)]);
                    bh[nt][1] = __float_as_uint(sWh[pW64(k8 + 4 + l4, n)]);
                    bl[nt][0] = __float_as_uint(sWl[pW64(k8 + l4, n)]);
                    bl[nt][1] = __float_as_uint(sWl[pW64(k8 + 4 + l4, n)]);
                }
#pragma unroll
                for (int mt = 0; mt < 4; mt++) {
                    int r0 = mw * 64 + mt * 16 + g;
                    uint32_t ah0 = __float_as_uint(sXh[pA8(r0, k8 + l4)]);
                    uint32_t ah1 = __float_as_uint(sXh[pA8(r0 + 8, k8 + l4)]);
                    uint32_t ah2 = __float_as_uint(sXh[pA8(r0, k8 + 4 + l4)]);
                    uint32_t ah3 = __float_as_uint(sXh[pA8(r0 + 8, k8 + 4 + l4)]);
                    uint32_t al0 = __float_as_uint(sXl[pA8(r0, k8 + l4)]);
                    uint32_t al1 = __float_as_uint(sXl[pA8(r0 + 8, k8 + l4)]);
                    uint32_t al2 = __float_as_uint(sXl[pA8(r0, k8 + 4 + l4)]);
                    uint32_t al3 = __float_as_uint(sXl[pA8(r0 + 8, k8 + 4 + l4)]);
#pragma unroll
                    for (int nt = 0; nt < 2; nt++) {
                        mma8(acc[mt][nt], ah0, ah1, ah2, ah3, bh[nt][0], bh[nt][1]);
                        mma8(acc[mt][nt], ah0, ah1, ah2, ah3, bl[nt][0], bl[nt][1]);
                        mma8(acc[mt][nt], al0, al1, al2, al3, bh[nt][0], bh[nt][1]);
                    }
                }
            }
            __syncthreads();
        }

        if (nw < 2) {
#pragma unroll
            for (int mt = 0; mt < 4; mt++) {
                int m = m0 + mw * 64 + mt * 16 + g;
#pragma unroll
                for (int nt = 0; nt < 2; nt++) {
                    int col = nw * 16 + nt * 8 + l4 * 2;
                    float2 bb = *(const float2*)(bq + col);
                    float2 o0, o1;
                    o0.x = acc[mt][nt][0] + bb.x;
                    o0.y = acc[mt][nt][1] + bb.y;
                    o1.x = acc[mt][nt][2] + bb.x;
                    o1.y = acc[mt][nt][3] + bb.y;
                    *(float2*)(Yq + (size_t)m * DDIM + col) = o0;
                    *(float2*)(Yq + (size_t)(m + 8) * DDIM + col) = o1;
                }
            }
        } else {
#pragma unroll
            for (int mt = 0; mt < 4; mt++) {
                int m = m0 + mw * 64 + mt * 16 + g;
#pragma unroll
                for (int nt = 0; nt < 2; nt++) {
                    int d = (nw - 2) * 16 + nt * 8 + l4 * 2;
                    int w = (nw - 2) * 8 + nt * 4 + l4;
                    float2 bb = *(const float2*)(bk + d);
                    {
                        float v0 = acc[mt][nt][0] + bb.x;
                        float v1 = acc[mt][nt][1] + bb.y;
                        size_t idx = (size_t)(m >> 6) * 1024 + pK16(m & 63, w);
                        ((uint32_t*)KTH)[idx] = bftruncpack(v0, v1);
                        ((uint32_t*)KTL)[idx] = bfpack(bftrunc_res(v0), bftrunc_res(v1));
                    }
                    {
                        float v0 = acc[mt][nt][2] + bb.x;
                        float v1 = acc[mt][nt][3] + bb.y;
                        int m8 = m + 8;
                        size_t idx = (size_t)(m8 >> 6) * 1024 + pK16(m8 & 63, w);
                        ((uint32_t*)KTH)[idx] = bftruncpack(v0, v1);
                        ((uint32_t*)KTL)[idx] = bfpack(bftrunc_res(v0), bftrunc_res(v1));
                    }
                }
            }
        }
    }
}

// ============================================================================
extern "C" void kernel_launch(void* const* d_in, const int* in_sizes, int n_in,
                              void* d_out, int out_size) {
    const float* x  = (const float*)d_in[0];
    const float* wq = (const float*)d_in[1];
    const float* bq = (const float*)d_in[2];
    const float* wk = (const float*)d_in[3];
    const float* bk = (const float*)d_in[4];
    const float* wv = (const float*)d_in[5];
    const float* bv = (const float*)d_in[6];
    float* out = (float*)d_out;

    float *qp, *kthp, *ktlp, *vp;
    cudaGetSymbolAddress((void**)&qp, g_q);
    cudaGetSymbolAddress((void**)&kthp, g_kth);
    cudaGetSymbolAddress((void**)&ktlp, g_ktl);
    cudaGetSymbolAddress((void**)&vp, g_v);

    {
        cudaFuncSetAttribute(proj_all, cudaFuncAttributeMaxDynamicSharedMemorySize, PROJ_SMEM);
        proj_all<<<384, 256, PROJ_SMEM>>>(x, wq, bq, wk, bk, wv, bv, qp, kthp, ktlp, vp);
    }
    {
        cudaFuncSetAttribute(flash_mma, cudaFuncAttributeMaxDynamicSharedMemorySize, FLASH_SMEM);
        dim3 g(SEQ / TQ, BATCH);
        flash_mma<<<g, 128, FLASH_SMEM>>>(qp, kthp, ktlp, vp, x, out);
    }
}